// round 11
// baseline (speedup 1.0000x reference)
#include <cuda_runtime.h>
#include <cuda_bf16.h>
#include <math.h>
#include <stdint.h>

#define B      8
#define S_P    128
#define S_T    64
#define S_V    64
#define SEQ    256
#define DMODEL 768
#define DLLM   4096
#define NH     32
#define HD     128
#define DFF    11008
#define NLAYER 2
#define NTOK   (B*SEQ)
#define EPSRMS 1e-5f

__device__ float g_h [NTOK*DLLM];
__device__ float g_x [NTOK*DLLM];
__device__ float g_q [NTOK*DLLM];
__device__ float g_k [NTOK*DLLM];
__device__ float g_v [NTOK*DLLM];
__device__ float g_o [NTOK*DLLM];
__device__ float g_sc[B*NH*SEQ*SEQ];
__device__ float g_ff[NTOK*DFF];
__device__ float g_pool[B*DLLM];
__device__ float g_y1[B*768];

__device__ __forceinline__ float siluf(float x) { return x / (1.f + expf(-x)); }

// ======================= mma.sync plumbing =======================
__device__ __forceinline__ uint32_t smem_u32(const void* p) {
    uint32_t a;
    asm("{ .reg .u64 t; cvta.to.shared.u64 t, %1; cvt.u32.u64 %0, t; }" : "=r"(a) : "l"(p));
    return a;
}
#define LDSM4(R0,R1,R2,R3,addr) \
    asm volatile("ldmatrix.sync.aligned.m8n8.x4.shared.b16 {%0,%1,%2,%3}, [%4];" \
                 : "=r"(R0),"=r"(R1),"=r"(R2),"=r"(R3) : "r"(addr))
#define MMA(d, a, b) \
    asm volatile("mma.sync.aligned.m16n8k16.row.col.f32.bf16.bf16.f32 " \
        "{%0,%1,%2,%3},{%4,%5,%6,%7},{%8,%9},{%0,%1,%2,%3};" \
        : "+f"((d)[0]),"+f"((d)[1]),"+f"((d)[2]),"+f"((d)[3]) \
        : "r"((a)[0]),"r"((a)[1]),"r"((a)[2]),"r"((a)[3]),"r"((b)[0]),"r"((b)[1]))

// fp32 -> (hi, lo) bf16 pairs; first arg in low 16 bits
__device__ __forceinline__ void split2(float a, float b, uint32_t& hi, uint32_t& lo) {
    __nv_bfloat162 h = __floats2bfloat162_rn(a, b);
    float2 hf = __bfloat1622float2(h);
    __nv_bfloat162 l = __floats2bfloat162_rn(a - hf.x, b - hf.y);
    hi = *reinterpret_cast<uint32_t*>(&h);
    lo = *reinterpret_cast<uint32_t*>(&l);
}

// Tile rows are 32 bf16 = 64B = four 16B chunks; XOR-swizzle chunks by row
// so ldmatrix 8-row phases hit all 32 banks (conflict-free).
__device__ __forceinline__ uint32_t swz(int r, int cChunk) {
    return (uint32_t)(r * 64 + (((cChunk) ^ ((r >> 1) & 3)) << 4));
}

// ====== split-bf16 tensor GEMM: C[M,N] (+)= A[M,K]@B[K,N], fp32 io ======
// CTA 128x128, K-stage 32, 256 thr (8 warps = 2m x 4n, warp tile 64x32).
// Double-buffered SMEM (2 x 32KB dynamic), ONE sync per stage.
// Term-major MMA order: 16 independent tiles per split-term -> no RAW chains.
// EPI: 0=store(+bias), 1=C+=acc, 2=C=silu(C)*acc.  orow=(r/rpbi)*rpbo+roff+r%rpbi
#define GSMEM 65536
template<int EPI>
__global__ __launch_bounds__(256)
void gemm_mma(int M, int N, int K,
              const float* __restrict__ A, const float* __restrict__ Bm,
              const float* __restrict__ bias, float* __restrict__ C,
              int rpbi, int rpbo, int roff)
{
    extern __shared__ __align__(16) char sm[];   // 2 x (ah|al|bh|bl) 8KB each
    const uint32_t sb = smem_u32(sm);
    const int tid = threadIdx.x, lane = tid & 31, wid = tid >> 5;
    const int gm0 = blockIdx.x * 128, gn0 = blockIdx.y * 128;
    const int wm = (wid & 1) * 64, wn = (wid >> 1) * 32;

    float acc[4][4][4] = {};

    // producer indices
    const int par = tid >> 3;                // A row base (+32p)
    const int pak = (tid & 7) * 4;           // A k elems (float4)
    const int pbk = wid * 2 + (lane >> 4);   // B k-pair 0..15
    const int pbn = (lane & 15) * 2;         // B n base (+32i)

    float4 aReg[4];
    float2 bReg[4][2];

    auto loadG = [&](int k0) {
        const float* Ag = A + (size_t)(gm0 + par) * K + k0 + pak;
        #pragma unroll
        for (int p = 0; p < 4; p++)
            aReg[p] = *(const float4*)(Ag + (size_t)(32 * p) * K);
        const float* Bg = Bm + (size_t)(k0 + 2 * pbk) * N + gn0 + pbn;
        #pragma unroll
        for (int i = 0; i < 4; i++) {
            bReg[i][0] = *(const float2*)(Bg + 32 * i);
            bReg[i][1] = *(const float2*)(Bg + N + 32 * i);
        }
    };
    auto storeS = [&](int b) {
        char* base = sm + b * 32768;
        #pragma unroll
        for (int p = 0; p < 4; p++) {
            int r = par + 32 * p;
            uint32_t h0, l0, h1, l1;
            split2(aReg[p].x, aReg[p].y, h0, l0);
            split2(aReg[p].z, aReg[p].w, h1, l1);
            uint32_t off = swz(r, pak >> 3) + ((pak & 4) << 1);
            *(uint2*)(base + off)        = make_uint2(h0, h1);
            *(uint2*)(base + 8192 + off) = make_uint2(l0, l1);
        }
        #pragma unroll
        for (int i = 0; i < 4; i++) {
            int n = pbn + 32 * i;
            uint32_t hp0, lp0, hp1, lp1;
            split2(bReg[i][0].x, bReg[i][1].x, hp0, lp0);   // (k, k+1) at n
            split2(bReg[i][0].y, bReg[i][1].y, hp1, lp1);   // (k, k+1) at n+1
            uint32_t inner = (uint32_t)((pbk & 3) << 2);
            uint32_t o0 = swz(n, pbk >> 2) + inner;
            uint32_t o1 = swz(n + 1, pbk >> 2) + inner;
            *(uint32_t*)(base + 16384 + o0) = hp0;
            *(uint32_t*)(base + 24576 + o0) = lp0;
            *(uint32_t*)(base + 16384 + o1) = hp1;
            *(uint32_t*)(base + 24576 + o1) = lp1;
        }
    };
    auto computeStage = [&](int b) {
        const uint32_t ahS = sb + b * 32768;
        #pragma unroll
        for (int half = 0; half < 2; half++) {
            uint32_t aH[4][4], aL[4][4], bH[4][2], bL[4][2];
            int cb = (half << 1) + (lane >> 4);
            #pragma unroll
            for (int mi = 0; mi < 4; mi++) {
                uint32_t off = swz(wm + mi * 16 + (lane & 15), cb);
                LDSM4(aH[mi][0], aH[mi][1], aH[mi][2], aH[mi][3], ahS + off);
                LDSM4(aL[mi][0], aL[mi][1], aL[mi][2], aL[mi][3], ahS + 8192 + off);
            }
            #pragma unroll
            for (int nh = 0; nh < 2; nh++) {
                uint32_t off = swz(wn + nh * 16 + (lane & 15), cb);
                uint32_t r0, r1, r2, r3;
                LDSM4(r0, r1, r2, r3, ahS + 16384 + off);
                bH[2*nh][0] = r0; bH[2*nh][1] = r2; bH[2*nh+1][0] = r1; bH[2*nh+1][1] = r3;
                LDSM4(r0, r1, r2, r3, ahS + 24576 + off);
                bL[2*nh][0] = r0; bL[2*nh][1] = r2; bL[2*nh+1][0] = r1; bL[2*nh+1][1] = r3;
            }
            // term-major: 16 independent MMAs per group, no acc RAW chains
            #pragma unroll
            for (int mi = 0; mi < 4; mi++)
                #pragma unroll
                for (int ni = 0; ni < 4; ni++)
                    MMA(acc[mi][ni], aH[mi], bH[ni]);
            #pragma unroll
            for (int mi = 0; mi < 4; mi++)
                #pragma unroll
                for (int ni = 0; ni < 4; ni++)
                    MMA(acc[mi][ni], aH[mi], bL[ni]);
            #pragma unroll
            for (int mi = 0; mi < 4; mi++)
                #pragma unroll
                for (int ni = 0; ni < 4; ni++)
                    MMA(acc[mi][ni], aL[mi], bH[ni]);
        }
    };

    const int nst = K / 32;
    // prologue: stage 0 into buf0, prefetch stage 1 regs
    loadG(0);
    storeS(0);
    loadG(32);
    __syncthreads();
    for (int s = 0; s < nst; s++) {
        if (s + 1 < nst) storeS((s + 1) & 1);   // regs hold stage s+1
        if (s + 2 < nst) loadG((s + 2) * 32);
        computeStage(s & 1);
        __syncthreads();
    }

    // ---- epilogue ----
    #pragma unroll
    for (int mi = 0; mi < 4; mi++) {
        int rbase = gm0 + wm + mi * 16 + (lane >> 2);
        #pragma unroll
        for (int half = 0; half < 2; half++) {
            int r = rbase + half * 8;
            int orow = (r / rpbi) * rpbo + roff + (r % rpbi);
            float* Crow = C + (size_t)orow * N;
            #pragma unroll
            for (int ni = 0; ni < 4; ni++) {
                int col = gn0 + wn + ni * 8 + (lane & 3) * 2;
                float v0 = acc[mi][ni][half * 2 + 0];
                float v1 = acc[mi][ni][half * 2 + 1];
                float* d = Crow + col;
                if (EPI == 0) {
                    if (bias) { v0 += bias[col]; v1 += bias[col + 1]; }
                    d[0] = v0; d[1] = v1;
                } else if (EPI == 1) {
                    d[0] += v0; d[1] += v1;
                } else {
                    d[0] = siluf(d[0]) * v0; d[1] = siluf(d[1]) * v1;
                }
            }
        }
    }
}

// ======================= auxiliary kernels (unchanged) =======================
__global__ __launch_bounds__(256)
void embed_kernel(const int* __restrict__ ids, const float* __restrict__ table,
                  float* __restrict__ h)
{
    int t = blockIdx.x;
    int b = t >> 7, p = t & 127;
    int id = ids[t];
    const float4* src = (const float4*)(table + (size_t)id * DLLM);
    float4* dst = (float4*)(h + ((size_t)b * SEQ + p) * DLLM);
    for (int i = threadIdx.x; i < DLLM / 4; i += 256) dst[i] = src[i];
}

__global__ __launch_bounds__(256)
void rmsnorm_kernel(const float* __restrict__ in, const float* __restrict__ w,
                    float* __restrict__ out)
{
    size_t t = blockIdx.x;
    const float4* xp = (const float4*)(in + t * DLLM);
    __shared__ float red[8];
    float ss = 0.f;
    for (int i = threadIdx.x; i < DLLM / 4; i += 256) {
        float4 v = xp[i];
        ss += v.x*v.x + v.y*v.y + v.z*v.z + v.w*v.w;
    }
    #pragma unroll
    for (int o = 16; o; o >>= 1) ss += __shfl_xor_sync(0xffffffffu, ss, o);
    if ((threadIdx.x & 31) == 0) red[threadIdx.x >> 5] = ss;
    __syncthreads();
    if (threadIdx.x < 32) {
        float v = (threadIdx.x < 8) ? red[threadIdx.x] : 0.f;
        #pragma unroll
        for (int o = 4; o; o >>= 1) v += __shfl_xor_sync(0xffffffffu, v, o);
        if (threadIdx.x == 0) red[0] = v;
    }
    __syncthreads();
    float r = rsqrtf(red[0] / (float)DLLM + EPSRMS);
    const float4* wp = (const float4*)w;
    float4* op = (float4*)(out + t * DLLM);
    for (int i = threadIdx.x; i < DLLM / 4; i += 256) {
        float4 v = xp[i], wv = wp[i];
        op[i] = make_float4(v.x*r*wv.x, v.y*r*wv.y, v.z*r*wv.z, v.w*r*wv.w);
    }
}

__global__ __launch_bounds__(256)
void rope_kernel(float* __restrict__ q, float* __restrict__ k)
{
    int t = blockIdx.x;
    int pos = t & (SEQ - 1);
    const float LOG_THETA = 9.210340371976184f;
    for (int it = 0; it < 8; it++) {
        int p = threadIdx.x + it * 256;
        int hh = p >> 6, j = p & 63;
        float inv_freq = expf(-(float)j * (LOG_THETA / 64.f));
        float ang = (float)pos * inv_freq;
        float c = cosf(ang), s = sinf(ang);
        size_t base = (size_t)t * DLLM + hh * HD + j;
        float x1 = q[base], x2 = q[base + 64];
        q[base]      = x1 * c - x2 * s;
        q[base + 64] = x2 * c + x1 * s;
        x1 = k[base]; x2 = k[base + 64];
        k[base]      = x1 * c - x2 * s;
        k[base + 64] = x2 * c + x1 * s;
    }
}

__global__ __launch_bounds__(256)
void score_kernel(const float* __restrict__ Q, const float* __restrict__ K,
                  float* __restrict__ Sc)
{
    int bh = blockIdx.z;
    int b = bh >> 5, hh = bh & 31;
    int qi0 = blockIdx.y * 64, kj0 = blockIdx.x * 64;
    __shared__ float As[16][64];
    __shared__ float Bs[16][64];
    int tid = threadIdx.x;
    int tx = tid & 15, ty = tid >> 4;
    float acc[4][4] = {};
    const float* Qb = Q + ((size_t)b * SEQ + qi0) * DLLM + hh * HD;
    const float* Kb = K + ((size_t)b * SEQ + kj0) * DLLM + hh * HD;
    int r  = tid >> 2;
    int c4 = (tid & 3) * 4;
    for (int k0 = 0; k0 < HD; k0 += 16) {
        float4 qa = *(const float4*)(Qb + (size_t)r * DLLM + k0 + c4);
        As[c4+0][r] = qa.x; As[c4+1][r] = qa.y; As[c4+2][r] = qa.z; As[c4+3][r] = qa.w;
        float4 ka = *(const float4*)(Kb + (size_t)r * DLLM + k0 + c4);
        Bs[c4+0][r] = ka.x; Bs[c4+1][r] = ka.y; Bs[c4+2][r] = ka.z; Bs[c4+3][r] = ka.w;
        __syncthreads();
        #pragma unroll
        for (int kk = 0; kk < 16; kk++) {
            float a[4], bb[4];
            *(float4*)a  = *(const float4*)&As[kk][ty * 4];
            *(float4*)bb = *(const float4*)&Bs[kk][tx * 4];
            #pragma unroll
            for (int i = 0; i < 4; i++)
                #pragma unroll
                for (int j = 0; j < 4; j++)
                    acc[i][j] = fmaf(a[i], bb[j], acc[i][j]);
        }
        __syncthreads();
    }
    const float scale = 0.08838834764831845f;
    #pragma unroll
    for (int i = 0; i < 4; i++) {
        int qi = qi0 + ty * 4 + i;
        float* dst = Sc + ((size_t)bh * SEQ + qi) * SEQ + kj0 + tx * 4;
        #pragma unroll
        for (int j = 0; j < 4; j++) {
            int kj = kj0 + tx * 4 + j;
            dst[j] = (kj > qi) ? -1e30f : acc[i][j] * scale;
        }
    }
}

__global__ __launch_bounds__(256)
void softmax_kernel(float* __restrict__ Sc)
{
    float* p = Sc + (size_t)blockIdx.x * SEQ;
    int tid = threadIdx.x;
    __shared__ float redm[8], reds[8];
    float v = p[tid];
    float m = v;
    #pragma unroll
    for (int o = 16; o; o >>= 1) m = fmaxf(m, __shfl_xor_sync(0xffffffffu, m, o));
    if ((tid & 31) == 0) redm[tid >> 5] = m;
    __syncthreads();
    if (tid < 32) {
        float x = (tid < 8) ? redm[tid] : -3.4e38f;
        #pragma unroll
        for (int o = 4; o; o >>= 1) x = fmaxf(x, __shfl_xor_sync(0xffffffffu, x, o));
        if (tid == 0) redm[0] = x;
    }
    __syncthreads();
    m = redm[0];
    float e = expf(v - m);
    float s = e;
    #pragma unroll
    for (int o = 16; o; o >>= 1) s += __shfl_xor_sync(0xffffffffu, s, o);
    if ((tid & 31) == 0) reds[tid >> 5] = s;
    __syncthreads();
    if (tid < 32) {
        float x = (tid < 8) ? reds[tid] : 0.f;
        #pragma unroll
        for (int o = 4; o; o >>= 1) x += __shfl_xor_sync(0xffffffffu, x, o);
        if (tid == 0) reds[0] = x;
    }
    __syncthreads();
    p[tid] = e / reds[0];
}

__global__ __launch_bounds__(256)
void av_kernel(const float* __restrict__ P, const float* __restrict__ V,
               float* __restrict__ O)
{
    int bh = blockIdx.y;
    int b = bh >> 5, hh = bh & 31;
    int qi0 = blockIdx.x * 64;
    __shared__ float Ps[16][64];
    __shared__ float Vs[16][128];
    int tid = threadIdx.x;
    int tx = tid & 31, ty = tid >> 5;
    float acc[8][4] = {};
    const float* Pb = P + ((size_t)bh * SEQ + qi0) * SEQ;
    const float* Vb = V + (size_t)b * SEQ * DLLM + hh * HD;
    int pq = tid >> 2, pk4 = (tid & 3) * 4;
    int vk = tid >> 4, vd8 = (tid & 15) * 8;
    for (int k0 = 0; k0 < SEQ; k0 += 16) {
        float4 pv = *(const float4*)(Pb + (size_t)pq * SEQ + k0 + pk4);
        Ps[pk4+0][pq] = pv.x; Ps[pk4+1][pq] = pv.y; Ps[pk4+2][pq] = pv.z; Ps[pk4+3][pq] = pv.w;
        const float* src = Vb + (size_t)(k0 + vk) * DLLM + vd8;
        *(float4*)&Vs[vk][vd8]     = *(const float4*)(src);
        *(float4*)&Vs[vk][vd8 + 4] = *(const float4*)(src + 4);
        __syncthreads();
        #pragma unroll
        for (int kk = 0; kk < 16; kk++) {
            float a[8], bb[4];
            *(float4*)(a)     = *(const float4*)&Ps[kk][ty * 8];
            *(float4*)(a + 4) = *(const float4*)&Ps[kk][ty * 8 + 4];
            *(float4*)bb      = *(const float4*)&Vs[kk][tx * 4];
            #pragma unroll
            for (int i = 0; i < 8; i++)
                #pragma unroll
                for (int j = 0; j < 4; j++)
                    acc[i][j] = fmaf(a[i], bb[j], acc[i][j]);
        }
        __syncthreads();
    }
    #pragma unroll
    for (int i = 0; i < 8; i++) {
        int qi = qi0 + ty * 8 + i;
        float* dst = O + ((size_t)b * SEQ + qi) * DLLM + hh * HD + tx * 4;
        *(float4*)dst = make_float4(acc[i][0], acc[i][1], acc[i][2], acc[i][3]);
    }
}

__global__ __launch_bounds__(256)
void pool_kernel(const float* __restrict__ x, float* __restrict__ pooled)
{
    int b = blockIdx.x;
    int d = blockIdx.y * 256 + threadIdx.x;
    float s = 0.f;
    const float* base = x + (size_t)b * SEQ * DLLM + d;
    for (int t = 0; t < SEQ; t++) s += base[(size_t)t * DLLM];
    pooled[(size_t)b * DLLM + d] = s * (1.f / SEQ);
}

__global__ __launch_bounds__(256)
void out1_kernel(const float* __restrict__ pooled, const float* __restrict__ W,
                 const float* __restrict__ bias, float* __restrict__ y1)
{
    int b = blockIdx.x;
    int n = blockIdx.y * 256 + threadIdx.x;
    const float* pv = pooled + (size_t)b * DLLM;
    float acc = bias[n];
    for (int k = 0; k < DLLM; k++)
        acc = fmaf(pv[k], W[(size_t)k * 768 + n], acc);
    y1[(size_t)b * 768 + n] = acc;
}

__global__ __launch_bounds__(256)
void out2_kernel(const float* __restrict__ y1, const float* __restrict__ W2,
                 const float* __restrict__ b2, float* __restrict__ out)
{
    int b = blockIdx.x;
    int tid = threadIdx.x;
    __shared__ float red[8];
    float s = 0.f;
    for (int j = tid; j < 768; j += 256) s += y1[(size_t)b * 768 + j] * W2[j];
    #pragma unroll
    for (int o = 16; o; o >>= 1) s += __shfl_xor_sync(0xffffffffu, s, o);
    if ((tid & 31) == 0) red[tid >> 5] = s;
    __syncthreads();
    if (tid < 32) {
        float x = (tid < 8) ? red[tid] : 0.f;
        #pragma unroll
        for (int o = 4; o; o >>= 1) x += __shfl_xor_sync(0xffffffffu, x, o);
        if (tid == 0) out[b] = x + b2[0];
    }
}

// ======================= host orchestration =======================
extern "C" void kernel_launch(void* const* d_in, const int* in_sizes, int n_in,
                              void* d_out, int out_size)
{
    const float* text    = (const float*)d_in[0];
    const float* vision  = (const float*)d_in[1];
    const int*   prompt  = (const int*)  d_in[2];
    const float* in_W    = (const float*)d_in[3];
    const float* in_b    = (const float*)d_in[4];
    const float* table   = (const float*)d_in[5];
    const float* Wq      = (const float*)d_in[6];
    const float* Wk      = (const float*)d_in[7];
    const float* Wv      = (const float*)d_in[8];
    const float* Wo      = (const float*)d_in[9];
    const float* ln1     = (const float*)d_in[10];
    const float* ln2     = (const float*)d_in[11];
    const float* Wg      = (const float*)d_in[12];
    const float* Wu      = (const float*)d_in[13];
    const float* Wd      = (const float*)d_in[14];
    const float* final_w = (const float*)d_in[15];
    const float* out1W   = (const float*)d_in[16];
    const float* out1b   = (const float*)d_in[17];
    const float* out2W   = (const float*)d_in[18];
    const float* out2b   = (const float*)d_in[19];
    float* out = (float*)d_out;

    float *h, *x, *q, *k, *v, *o, *sc, *ff, *pooled, *y1;
    cudaGetSymbolAddress((void**)&h,  g_h);
    cudaGetSymbolAddress((void**)&x,  g_x);
    cudaGetSymbolAddress((void**)&q,  g_q);
    cudaGetSymbolAddress((void**)&k,  g_k);
    cudaGetSymbolAddress((void**)&v,  g_v);
    cudaGetSymbolAddress((void**)&o,  g_o);
    cudaGetSymbolAddress((void**)&sc, g_sc);
    cudaGetSymbolAddress((void**)&ff, g_ff);
    cudaGetSymbolAddress((void**)&pooled, g_pool);
    cudaGetSymbolAddress((void**)&y1, g_y1);

    static int smem_set = 0;
    if (!smem_set) {
        cudaFuncSetAttribute(gemm_mma<0>, cudaFuncAttributeMaxDynamicSharedMemorySize, GSMEM);
        cudaFuncSetAttribute(gemm_mma<1>, cudaFuncAttributeMaxDynamicSharedMemorySize, GSMEM);
        cudaFuncSetAttribute(gemm_mma<2>, cudaFuncAttributeMaxDynamicSharedMemorySize, GSMEM);
        smem_set = 1;
    }

    // ---- inputs into concatenated h: [prompt(128) | text(64) | vision(64)] ----
    embed_kernel<<<B * S_P, 256>>>(prompt, table, h);
    gemm_mma<0><<<dim3((B*S_T)/128, DLLM/128), 256, GSMEM>>>(
        B*S_T, DLLM, DMODEL, text,   in_W, in_b, h, S_T, SEQ, S_P);
    gemm_mma<0><<<dim3((B*S_V)/128, DLLM/128), 256, GSMEM>>>(
        B*S_V, DLLM, DMODEL, vision, in_W, in_b, h, S_V, SEQ, S_P + S_T);

    for (int l = 0; l < NLAYER; l++) {
        const float* wq = Wq + (size_t)l * DLLM * DLLM;
        const float* wk = Wk + (size_t)l * DLLM * DLLM;
        const float* wv = Wv + (size_t)l * DLLM * DLLM;
        const float* wo = Wo + (size_t)l * DLLM * DLLM;
        const float* wg = Wg + (size_t)l * DLLM * DFF;
        const float* wu = Wu + (size_t)l * DLLM * DFF;
        const float* wd = Wd + (size_t)l * DFF * DLLM;
        const float* l1 = ln1 + (size_t)l * DLLM;
        const float* l2 = ln2 + (size_t)l * DLLM;

        rmsnorm_kernel<<<NTOK, 256>>>(h, l1, x);
        gemm_mma<0><<<dim3(NTOK/128, DLLM/128), 256, GSMEM>>>(NTOK, DLLM, DLLM, x, wq, nullptr, q, NTOK, NTOK, 0);
        gemm_mma<0><<<dim3(NTOK/128, DLLM/128), 256, GSMEM>>>(NTOK, DLLM, DLLM, x, wk, nullptr, k, NTOK, NTOK, 0);
        gemm_mma<0><<<dim3(NTOK/128, DLLM/128), 256, GSMEM>>>(NTOK, DLLM, DLLM, x, wv, nullptr, v, NTOK, NTOK, 0);
        rope_kernel<<<NTOK, 256>>>(q, k);
        score_kernel<<<dim3(SEQ/64, SEQ/64, B*NH), 256>>>(q, k, sc);
        softmax_kernel<<<B*NH*SEQ, 256>>>(sc);
        av_kernel<<<dim3(SEQ/64, B*NH), 256>>>(sc, v, o);
        gemm_mma<1><<<dim3(NTOK/128, DLLM/128), 256, GSMEM>>>(NTOK, DLLM, DLLM, o, wo, nullptr, h, NTOK, NTOK, 0);

        rmsnorm_kernel<<<NTOK, 256>>>(h, l2, x);
        gemm_mma<0><<<dim3(NTOK/128, DFF/128), 256, GSMEM>>>(NTOK, DFF, DLLM, x, wg, nullptr, ff, NTOK, NTOK, 0);
        gemm_mma<2><<<dim3(NTOK/128, DFF/128), 256, GSMEM>>>(NTOK, DFF, DLLM, x, wu, nullptr, ff, NTOK, NTOK, 0);
        gemm_mma<1><<<dim3(NTOK/128, DLLM/128), 256, GSMEM>>>(NTOK, DLLM, DFF, ff, wd, nullptr, h, NTOK, NTOK, 0);
    }

    rmsnorm_kernel<<<NTOK, 256>>>(h, final_w, x);
    pool_kernel<<<dim3(B, DLLM/256), 256>>>(x, pooled);
    out1_kernel<<<dim3(B, 768/256), 256>>>(pooled, out1W, out1b, y1);
    out2_kernel<<<B, 256>>>(y1, out2W, out2b, out);
}

// round 12
// speedup vs baseline: 1.2993x; 1.2993x over previous
#include <cuda_runtime.h>
#include <cuda_bf16.h>
#include <math.h>
#include <stdint.h>

#define B      8
#define S_P    128
#define S_T    64
#define S_V    64
#define SEQ    256
#define DMODEL 768
#define DLLM   4096
#define NH     32
#define HD     128
#define DFF    11008
#define NLAYER 2
#define NTOK   (B*SEQ)
#define EPSRMS 1e-5f

__device__ float g_h  [NTOK*DLLM];
__device__ float g_x  [NTOK*DLLM];
__device__ float g_q  [NTOK*DLLM];
__device__ float g_k  [NTOK*DLLM];
__device__ float g_v  [NTOK*DLLM];
__device__ float g_o  [NTOK*DLLM];
__device__ float g_sc [B*NH*SEQ*SEQ];
__device__ float g_ff [NTOK*DFF];
__device__ float g_ff2[NTOK*DFF];
__device__ float g_pool[B*DLLM];
__device__ float g_y1[B*768];

__device__ __forceinline__ float siluf(float x) { return x / (1.f + expf(-x)); }

// ======================= mma.sync plumbing =======================
__device__ __forceinline__ uint32_t smem_u32(const void* p) {
    uint32_t a;
    asm("{ .reg .u64 t; cvta.to.shared.u64 t, %1; cvt.u32.u64 %0, t; }" : "=r"(a) : "l"(p));
    return a;
}
#define LDSM4(R0,R1,R2,R3,addr) \
    asm volatile("ldmatrix.sync.aligned.m8n8.x4.shared.b16 {%0,%1,%2,%3}, [%4];" \
                 : "=r"(R0),"=r"(R1),"=r"(R2),"=r"(R3) : "r"(addr))
#define MMA(d, a, b) \
    asm volatile("mma.sync.aligned.m16n8k16.row.col.f32.bf16.bf16.f32 " \
        "{%0,%1,%2,%3},{%4,%5,%6,%7},{%8,%9},{%0,%1,%2,%3};" \
        : "+f"((d)[0]),"+f"((d)[1]),"+f"((d)[2]),"+f"((d)[3]) \
        : "r"((a)[0]),"r"((a)[1]),"r"((a)[2]),"r"((a)[3]),"r"((b)[0]),"r"((b)[1]))

// fp32 -> (hi, lo) bf16 pairs; first arg in low 16 bits
__device__ __forceinline__ void split2(float a, float b, uint32_t& hi, uint32_t& lo) {
    __nv_bfloat162 h = __floats2bfloat162_rn(a, b);
    float2 hf = __bfloat1622float2(h);
    __nv_bfloat162 l = __floats2bfloat162_rn(a - hf.x, b - hf.y);
    hi = *reinterpret_cast<uint32_t*>(&h);
    lo = *reinterpret_cast<uint32_t*>(&l);
}

// Tile rows are 32 bf16 = 64B = four 16B chunks; XOR-swizzle chunks by row
// so ldmatrix 8-row phases hit all 32 banks (conflict-free).
__device__ __forceinline__ uint32_t swz(int r, int cChunk) {
    return (uint32_t)(r * 64 + (((cChunk) ^ ((r >> 1) & 3)) << 4));
}

// ====== split-bf16 tensor GEMM: C[M,N] (+)= A[M,K]@B[K,N], fp32 io ======
// CTA 128x128, K-stage 32, 256 thr (8 warps = 2m x 4n, warp tile 64x32).
// 2 CTAs/SM (launch_bounds 256,2): sibling CTA fills barrier/producer gaps.
// grid.z selects (B, C) from {b0,c0 | b1,c1 | b2,c2} for merged launches.
// FUSEA: A = silu(A[.]) * A2[.] computed in the producer (SwiGLU fusion).
// EPI: 0=store(+bias), 1=C+=acc.  orow = (r/rpbi)*rpbo + roff + r%rpbi
template<int EPI, bool FUSEA>
__global__ __launch_bounds__(256, 2)
void gemm_mma(int M, int N, int K,
              const float* __restrict__ A, const float* __restrict__ A2,
              const float* __restrict__ b0, const float* __restrict__ b1,
              const float* __restrict__ b2,
              const float* __restrict__ bias,
              float* __restrict__ c0, float* __restrict__ c1, float* __restrict__ c2,
              int rpbi, int rpbo, int roff)
{
    const float* Bm = (blockIdx.z == 0) ? b0 : ((blockIdx.z == 1) ? b1 : b2);
    float*       C  = (blockIdx.z == 0) ? c0 : ((blockIdx.z == 1) ? c1 : c2);

    __shared__ __align__(16) char sm[32768];   // ah | al | bh | bl (8KB each)
    const uint32_t sb = smem_u32(sm);
    const uint32_t ahS = sb, alS = sb + 8192, bhS = sb + 16384, blS = sb + 24576;
    const int tid = threadIdx.x, lane = tid & 31, wid = tid >> 5;
    const int gm0 = blockIdx.x * 128, gn0 = blockIdx.y * 128;
    const int wm = (wid & 1) * 64, wn = (wid >> 1) * 32;

    float acc[4][4][4] = {};

    // producer indices
    const int par = tid >> 3;                // A row base (+32p)
    const int pak = (tid & 7) * 4;           // A k elems (float4)
    const int pbk = wid * 2 + (lane >> 4);   // B k-pair 0..15
    const int pbn = (lane & 15) * 2;         // B n base (+32i)

    const int nst = K / 32;
    for (int s = 0; s < nst; s++) {
        const int k0 = s * 32;
        // ---- global loads (regs local to this stage) ----
        float4 aReg[4];
        float2 bReg[4][2];
        {
            const size_t aoff = (size_t)(gm0 + par) * K + k0 + pak;
            #pragma unroll
            for (int p = 0; p < 4; p++) {
                float4 v = *(const float4*)(A + aoff + (size_t)(32 * p) * K);
                if (FUSEA) {
                    float4 u = *(const float4*)(A2 + aoff + (size_t)(32 * p) * K);
                    v.x = siluf(v.x) * u.x; v.y = siluf(v.y) * u.y;
                    v.z = siluf(v.z) * u.z; v.w = siluf(v.w) * u.w;
                }
                aReg[p] = v;
            }
            const float* Bg = Bm + (size_t)(k0 + 2 * pbk) * N + gn0 + pbn;
            #pragma unroll
            for (int i = 0; i < 4; i++) {
                bReg[i][0] = *(const float2*)(Bg + 32 * i);
                bReg[i][1] = *(const float2*)(Bg + N + 32 * i);
            }
        }
        __syncthreads();   // prior stage's consumers done (WAR)
        // ---- split + store to smem ----
        #pragma unroll
        for (int p = 0; p < 4; p++) {
            int r = par + 32 * p;
            uint32_t h0, l0, h1, l1;
            split2(aReg[p].x, aReg[p].y, h0, l0);
            split2(aReg[p].z, aReg[p].w, h1, l1);
            uint32_t off = swz(r, pak >> 3) + ((pak & 4) << 1);
            *(uint2*)(sm + off)        = make_uint2(h0, h1);
            *(uint2*)(sm + 8192 + off) = make_uint2(l0, l1);
        }
        #pragma unroll
        for (int i = 0; i < 4; i++) {
            int n = pbn + 32 * i;
            uint32_t hp0, lp0, hp1, lp1;
            split2(bReg[i][0].x, bReg[i][1].x, hp0, lp0);   // (k, k+1) at n
            split2(bReg[i][0].y, bReg[i][1].y, hp1, lp1);   // (k, k+1) at n+1
            uint32_t inner = (uint32_t)((pbk & 3) << 2);
            uint32_t o0 = swz(n, pbk >> 2) + inner;
            uint32_t o1 = swz(n + 1, pbk >> 2) + inner;
            *(uint32_t*)(sm + 16384 + o0) = hp0;
            *(uint32_t*)(sm + 24576 + o0) = lp0;
            *(uint32_t*)(sm + 16384 + o1) = hp1;
            *(uint32_t*)(sm + 24576 + o1) = lp1;
        }
        __syncthreads();
        // ---- consume: two k16 halves ----
        #pragma unroll
        for (int half = 0; half < 2; half++) {
            uint32_t aH[4][4], aL[4][4], bH[4][2], bL[4][2];
            int cb = (half << 1) + (lane >> 4);
            #pragma unroll
            for (int mi = 0; mi < 4; mi++) {
                uint32_t off = swz(wm + mi * 16 + (lane & 15), cb);
                LDSM4(aH[mi][0], aH[mi][1], aH[mi][2], aH[mi][3], ahS + off);
                LDSM4(aL[mi][0], aL[mi][1], aL[mi][2], aL[mi][3], alS + off);
            }
            #pragma unroll
            for (int nh = 0; nh < 2; nh++) {
                uint32_t off = swz(wn + nh * 16 + (lane & 15), cb);
                uint32_t r0, r1, r2, r3;
                LDSM4(r0, r1, r2, r3, bhS + off);
                bH[2*nh][0] = r0; bH[2*nh][1] = r2; bH[2*nh+1][0] = r1; bH[2*nh+1][1] = r3;
                LDSM4(r0, r1, r2, r3, blS + off);
                bL[2*nh][0] = r0; bL[2*nh][1] = r2; bL[2*nh+1][0] = r1; bL[2*nh+1][1] = r3;
            }
            #pragma unroll
            for (int mi = 0; mi < 4; mi++)
                #pragma unroll
                for (int ni = 0; ni < 4; ni++) {
                    MMA(acc[mi][ni], aH[mi], bH[ni]);
                    MMA(acc[mi][ni], aH[mi], bL[ni]);
                    MMA(acc[mi][ni], aL[mi], bH[ni]);
                }
        }
    }

    // ---- epilogue ----
    #pragma unroll
    for (int mi = 0; mi < 4; mi++) {
        int rbase = gm0 + wm + mi * 16 + (lane >> 2);
        #pragma unroll
        for (int half = 0; half < 2; half++) {
            int r = rbase + half * 8;
            int orow = (r / rpbi) * rpbo + roff + (r % rpbi);
            float* Crow = C + (size_t)orow * N;
            #pragma unroll
            for (int ni = 0; ni < 4; ni++) {
                int col = gn0 + wn + ni * 8 + (lane & 3) * 2;
                float v0 = acc[mi][ni][half * 2 + 0];
                float v1 = acc[mi][ni][half * 2 + 1];
                float* d = Crow + col;
                if (EPI == 0) {
                    if (bias) { v0 += bias[col]; v1 += bias[col + 1]; }
                    d[0] = v0; d[1] = v1;
                } else {
                    d[0] += v0; d[1] += v1;
                }
            }
        }
    }
}

// ======================= auxiliary kernels (unchanged) =======================
__global__ __launch_bounds__(256)
void embed_kernel(const int* __restrict__ ids, const float* __restrict__ table,
                  float* __restrict__ h)
{
    int t = blockIdx.x;
    int b = t >> 7, p = t & 127;
    int id = ids[t];
    const float4* src = (const float4*)(table + (size_t)id * DLLM);
    float4* dst = (float4*)(h + ((size_t)b * SEQ + p) * DLLM);
    for (int i = threadIdx.x; i < DLLM / 4; i += 256) dst[i] = src[i];
}

__global__ __launch_bounds__(256)
void rmsnorm_kernel(const float* __restrict__ in, const float* __restrict__ w,
                    float* __restrict__ out)
{
    size_t t = blockIdx.x;
    const float4* xp = (const float4*)(in + t * DLLM);
    __shared__ float red[8];
    float ss = 0.f;
    for (int i = threadIdx.x; i < DLLM / 4; i += 256) {
        float4 v = xp[i];
        ss += v.x*v.x + v.y*v.y + v.z*v.z + v.w*v.w;
    }
    #pragma unroll
    for (int o = 16; o; o >>= 1) ss += __shfl_xor_sync(0xffffffffu, ss, o);
    if ((threadIdx.x & 31) == 0) red[threadIdx.x >> 5] = ss;
    __syncthreads();
    if (threadIdx.x < 32) {
        float v = (threadIdx.x < 8) ? red[threadIdx.x] : 0.f;
        #pragma unroll
        for (int o = 4; o; o >>= 1) v += __shfl_xor_sync(0xffffffffu, v, o);
        if (threadIdx.x == 0) red[0] = v;
    }
    __syncthreads();
    float r = rsqrtf(red[0] / (float)DLLM + EPSRMS);
    const float4* wp = (const float4*)w;
    float4* op = (float4*)(out + t * DLLM);
    for (int i = threadIdx.x; i < DLLM / 4; i += 256) {
        float4 v = xp[i], wv = wp[i];
        op[i] = make_float4(v.x*r*wv.x, v.y*r*wv.y, v.z*r*wv.z, v.w*r*wv.w);
    }
}

__global__ __launch_bounds__(256)
void rope_kernel(float* __restrict__ q, float* __restrict__ k)
{
    int t = blockIdx.x;
    int pos = t & (SEQ - 1);
    const float LOG_THETA = 9.210340371976184f;
    for (int it = 0; it < 8; it++) {
        int p = threadIdx.x + it * 256;
        int hh = p >> 6, j = p & 63;
        float inv_freq = expf(-(float)j * (LOG_THETA / 64.f));
        float ang = (float)pos * inv_freq;
        float c = cosf(ang), s = sinf(ang);
        size_t base = (size_t)t * DLLM + hh * HD + j;
        float x1 = q[base], x2 = q[base + 64];
        q[base]      = x1 * c - x2 * s;
        q[base + 64] = x2 * c + x1 * s;
        x1 = k[base]; x2 = k[base + 64];
        k[base]      = x1 * c - x2 * s;
        k[base + 64] = x2 * c + x1 * s;
    }
}

__global__ __launch_bounds__(256)
void score_kernel(const float* __restrict__ Q, const float* __restrict__ K,
                  float* __restrict__ Sc)
{
    int bh = blockIdx.z;
    int b = bh >> 5, hh = bh & 31;
    int qi0 = blockIdx.y * 64, kj0 = blockIdx.x * 64;
    __shared__ float As[16][64];
    __shared__ float Bs[16][64];
    int tid = threadIdx.x;
    int tx = tid & 15, ty = tid >> 4;
    float acc[4][4] = {};
    const float* Qb = Q + ((size_t)b * SEQ + qi0) * DLLM + hh * HD;
    const float* Kb = K + ((size_t)b * SEQ + kj0) * DLLM + hh * HD;
    int r  = tid >> 2;
    int c4 = (tid & 3) * 4;
    for (int k0 = 0; k0 < HD; k0 += 16) {
        float4 qa = *(const float4*)(Qb + (size_t)r * DLLM + k0 + c4);
        As[c4+0][r] = qa.x; As[c4+1][r] = qa.y; As[c4+2][r] = qa.z; As[c4+3][r] = qa.w;
        float4 ka = *(const float4*)(Kb + (size_t)r * DLLM + k0 + c4);
        Bs[c4+0][r] = ka.x; Bs[c4+1][r] = ka.y; Bs[c4+2][r] = ka.z; Bs[c4+3][r] = ka.w;
        __syncthreads();
        #pragma unroll
        for (int kk = 0; kk < 16; kk++) {
            float a[4], bb[4];
            *(float4*)a  = *(const float4*)&As[kk][ty * 4];
            *(float4*)bb = *(const float4*)&Bs[kk][tx * 4];
            #pragma unroll
            for (int i = 0; i < 4; i++)
                #pragma unroll
                for (int j = 0; j < 4; j++)
                    acc[i][j] = fmaf(a[i], bb[j], acc[i][j]);
        }
        __syncthreads();
    }
    const float scale = 0.08838834764831845f;
    #pragma unroll
    for (int i = 0; i < 4; i++) {
        int qi = qi0 + ty * 4 + i;
        float* dst = Sc + ((size_t)bh * SEQ + qi) * SEQ + kj0 + tx * 4;
        #pragma unroll
        for (int j = 0; j < 4; j++) {
            int kj = kj0 + tx * 4 + j;
            dst[j] = (kj > qi) ? -1e30f : acc[i][j] * scale;
        }
    }
}

__global__ __launch_bounds__(256)
void softmax_kernel(float* __restrict__ Sc)
{
    float* p = Sc + (size_t)blockIdx.x * SEQ;
    int tid = threadIdx.x;
    __shared__ float redm[8], reds[8];
    float v = p[tid];
    float m = v;
    #pragma unroll
    for (int o = 16; o; o >>= 1) m = fmaxf(m, __shfl_xor_sync(0xffffffffu, m, o));
    if ((tid & 31) == 0) redm[tid >> 5] = m;
    __syncthreads();
    if (tid < 32) {
        float x = (tid < 8) ? redm[tid] : -3.4e38f;
        #pragma unroll
        for (int o = 4; o; o >>= 1) x = fmaxf(x, __shfl_xor_sync(0xffffffffu, x, o));
        if (tid == 0) redm[0] = x;
    }
    __syncthreads();
    m = redm[0];
    float e = expf(v - m);
    float s = e;
    #pragma unroll
    for (int o = 16; o; o >>= 1) s += __shfl_xor_sync(0xffffffffu, s, o);
    if ((tid & 31) == 0) reds[tid >> 5] = s;
    __syncthreads();
    if (tid < 32) {
        float x = (tid < 8) ? reds[tid] : 0.f;
        #pragma unroll
        for (int o = 4; o; o >>= 1) x += __shfl_xor_sync(0xffffffffu, x, o);
        if (tid == 0) reds[0] = x;
    }
    __syncthreads();
    p[tid] = e / reds[0];
}

__global__ __launch_bounds__(256)
void av_kernel(const float* __restrict__ P, const float* __restrict__ V,
               float* __restrict__ O)
{
    int bh = blockIdx.y;
    int b = bh >> 5, hh = bh & 31;
    int qi0 = blockIdx.x * 64;
    __shared__ float Ps[16][64];
    __shared__ float Vs[16][128];
    int tid = threadIdx.x;
    int tx = tid & 31, ty = tid >> 5;
    float acc[8][4] = {};
    const float* Pb = P + ((size_t)bh * SEQ + qi0) * SEQ;
    const float* Vb = V + (size_t)b * SEQ * DLLM + hh * HD;
    int pq = tid >> 2, pk4 = (tid & 3) * 4;
    int vk = tid >> 4, vd8 = (tid & 15) * 8;
    for (int k0 = 0; k0 < SEQ; k0 += 16) {
        float4 pv = *(const float4*)(Pb + (size_t)pq * SEQ + k0 + pk4);
        Ps[pk4+0][pq] = pv.x; Ps[pk4+1][pq] = pv.y; Ps[pk4+2][pq] = pv.z; Ps[pk4+3][pq] = pv.w;
        const float* src = Vb + (size_t)(k0 + vk) * DLLM + vd8;
        *(float4*)&Vs[vk][vd8]     = *(const float4*)(src);
        *(float4*)&Vs[vk][vd8 + 4] = *(const float4*)(src + 4);
        __syncthreads();
        #pragma unroll
        for (int kk = 0; kk < 16; kk++) {
            float a[8], bb[4];
            *(float4*)(a)     = *(const float4*)&Ps[kk][ty * 8];
            *(float4*)(a + 4) = *(const float4*)&Ps[kk][ty * 8 + 4];
            *(float4*)bb      = *(const float4*)&Vs[kk][tx * 4];
            #pragma unroll
            for (int i = 0; i < 8; i++)
                #pragma unroll
                for (int j = 0; j < 4; j++)
                    acc[i][j] = fmaf(a[i], bb[j], acc[i][j]);
        }
        __syncthreads();
    }
    #pragma unroll
    for (int i = 0; i < 8; i++) {
        int qi = qi0 + ty * 8 + i;
        float* dst = O + ((size_t)b * SEQ + qi) * DLLM + hh * HD + tx * 4;
        *(float4*)dst = make_float4(acc[i][0], acc[i][1], acc[i][2], acc[i][3]);
    }
}

__global__ __launch_bounds__(256)
void pool_kernel(const float* __restrict__ x, float* __restrict__ pooled)
{
    int b = blockIdx.x;
    int d = blockIdx.y * 256 + threadIdx.x;
    float s = 0.f;
    const float* base = x + (size_t)b * SEQ * DLLM + d;
    for (int t = 0; t < SEQ; t++) s += base[(size_t)t * DLLM];
    pooled[(size_t)b * DLLM + d] = s * (1.f / SEQ);
}

__global__ __launch_bounds__(256)
void out1_kernel(const float* __restrict__ pooled, const float* __restrict__ W,
                 const float* __restrict__ bias, float* __restrict__ y1)
{
    int b = blockIdx.x;
    int n = blockIdx.y * 256 + threadIdx.x;
    const float* pv = pooled + (size_t)b * DLLM;
    float acc = bias[n];
    for (int k = 0; k < DLLM; k++)
        acc = fmaf(pv[k], W[(size_t)k * 768 + n], acc);
    y1[(size_t)b * 768 + n] = acc;
}

__global__ __launch_bounds__(256)
void out2_kernel(const float* __restrict__ y1, const float* __restrict__ W2,
                 const float* __restrict__ b2, float* __restrict__ out)
{
    int b = blockIdx.x;
    int tid = threadIdx.x;
    __shared__ float red[8];
    float s = 0.f;
    for (int j = tid; j < 768; j += 256) s += y1[(size_t)b * 768 + j] * W2[j];
    #pragma unroll
    for (int o = 16; o; o >>= 1) s += __shfl_xor_sync(0xffffffffu, s, o);
    if ((tid & 31) == 0) red[tid >> 5] = s;
    __syncthreads();
    if (tid < 32) {
        float x = (tid < 8) ? red[tid] : 0.f;
        #pragma unroll
        for (int o = 4; o; o >>= 1) x += __shfl_xor_sync(0xffffffffu, x, o);
        if (tid == 0) out[b] = x + b2[0];
    }
}

// ======================= host orchestration =======================
extern "C" void kernel_launch(void* const* d_in, const int* in_sizes, int n_in,
                              void* d_out, int out_size)
{
    const float* text    = (const float*)d_in[0];
    const float* vision  = (const float*)d_in[1];
    const int*   prompt  = (const int*)  d_in[2];
    const float* in_W    = (const float*)d_in[3];
    const float* in_b    = (const float*)d_in[4];
    const float* table   = (const float*)d_in[5];
    const float* Wq      = (const float*)d_in[6];
    const float* Wk      = (const float*)d_in[7];
    const float* Wv      = (const float*)d_in[8];
    const float* Wo      = (const float*)d_in[9];
    const float* ln1     = (const float*)d_in[10];
    const float* ln2     = (const float*)d_in[11];
    const float* Wg      = (const float*)d_in[12];
    const float* Wu      = (const float*)d_in[13];
    const float* Wd      = (const float*)d_in[14];
    const float* final_w = (const float*)d_in[15];
    const float* out1W   = (const float*)d_in[16];
    const float* out1b   = (const float*)d_in[17];
    const float* out2W   = (const float*)d_in[18];
    const float* out2b   = (const float*)d_in[19];
    float* out = (float*)d_out;

    float *h, *x, *q, *k, *v, *o, *sc, *ff, *ff2, *pooled, *y1;
    cudaGetSymbolAddress((void**)&h,   g_h);
    cudaGetSymbolAddress((void**)&x,   g_x);
    cudaGetSymbolAddress((void**)&q,   g_q);
    cudaGetSymbolAddress((void**)&k,   g_k);
    cudaGetSymbolAddress((void**)&v,   g_v);
    cudaGetSymbolAddress((void**)&o,   g_o);
    cudaGetSymbolAddress((void**)&sc,  g_sc);
    cudaGetSymbolAddress((void**)&ff,  g_ff);
    cudaGetSymbolAddress((void**)&ff2, g_ff2);
    cudaGetSymbolAddress((void**)&pooled, g_pool);
    cudaGetSymbolAddress((void**)&y1,  g_y1);

    // ---- inputs into concatenated h: [prompt(128) | text(64) | vision(64)] ----
    embed_kernel<<<B * S_P, 256>>>(prompt, table, h);
    gemm_mma<0,false><<<dim3((B*S_T)/128, DLLM/128, 1), 256>>>(
        B*S_T, DLLM, DMODEL, text, nullptr, in_W, in_W, in_W, in_b,
        h, h, h, S_T, SEQ, S_P);
    gemm_mma<0,false><<<dim3((B*S_V)/128, DLLM/128, 1), 256>>>(
        B*S_V, DLLM, DMODEL, vision, nullptr, in_W, in_W, in_W, in_b,
        h, h, h, S_V, SEQ, S_P + S_T);

    for (int l = 0; l < NLAYER; l++) {
        const float* wq = Wq + (size_t)l * DLLM * DLLM;
        const float* wk = Wk + (size_t)l * DLLM * DLLM;
        const float* wv = Wv + (size_t)l * DLLM * DLLM;
        const float* wo = Wo + (size_t)l * DLLM * DLLM;
        const float* wg = Wg + (size_t)l * DLLM * DFF;
        const float* wu = Wu + (size_t)l * DLLM * DFF;
        const float* wd = Wd + (size_t)l * DFF * DLLM;
        const float* l1 = ln1 + (size_t)l * DLLM;
        const float* l2 = ln2 + (size_t)l * DLLM;

        // --- attention block ---
        rmsnorm_kernel<<<NTOK, 256>>>(h, l1, x);
        // fused QKV: grid.z selects weight/output
        gemm_mma<0,false><<<dim3(NTOK/128, DLLM/128, 3), 256>>>(
            NTOK, DLLM, DLLM, x, nullptr, wq, wk, wv, nullptr,
            q, k, v, NTOK, NTOK, 0);
        rope_kernel<<<NTOK, 256>>>(q, k);
        score_kernel<<<dim3(SEQ/64, SEQ/64, B*NH), 256>>>(q, k, sc);
        softmax_kernel<<<B*NH*SEQ, 256>>>(sc);
        av_kernel<<<dim3(SEQ/64, B*NH), 256>>>(sc, v, o);
        gemm_mma<1,false><<<dim3(NTOK/128, DLLM/128, 1), 256>>>(
            NTOK, DLLM, DLLM, o, nullptr, wo, wo, wo, nullptr,
            h, h, h, NTOK, NTOK, 0);

        // --- FFN block: fused gate+up, SwiGLU folded into Wd's A producer ---
        rmsnorm_kernel<<<NTOK, 256>>>(h, l2, x);
        gemm_mma<0,false><<<dim3(NTOK/128, DFF/128, 2), 256>>>(
            NTOK, DFF, DLLM, x, nullptr, wg, wu, wu, nullptr,
            ff, ff2, ff2, NTOK, NTOK, 0);
        gemm_mma<1,true><<<dim3(NTOK/128, DLLM/128, 1), 256>>>(
            NTOK, DLLM, DFF, ff, ff2, wd, wd, wd, nullptr,
            h, h, h, NTOK, NTOK, 0);
    }

    rmsnorm_kernel<<<NTOK, 256>>>(h, final_w, x);
    pool_kernel<<<dim3(B, DLLM/256), 256>>>(x, pooled);
    out1_kernel<<<dim3(B, 768/256), 256>>>(pooled, out1W, out1b, y1);
    out2_kernel<<<B, 256>>>(y1, out2W, out2b, out);
}

// round 14
// speedup vs baseline: 1.4708x; 1.1320x over previous
#include <cuda_runtime.h>
#include <cuda_bf16.h>
#include <math.h>
#include <stdint.h>

#define B      8
#define S_P    128
#define S_T    64
#define S_V    64
#define SEQ    256
#define DMODEL 768
#define DLLM   4096
#define NH     32
#define HD     128
#define DFF    11008
#define NLAYER 2
#define NTOK   (B*SEQ)
#define EPSRMS 1e-5f

__device__ float g_h  [NTOK*DLLM];
__device__ float g_q  [NTOK*DLLM];
__device__ float g_k  [NTOK*DLLM];
__device__ float g_v  [NTOK*DLLM];
__device__ float g_sc [B*NH*SEQ*SEQ];
__device__ float g_ff [NTOK*DFF];
__device__ float g_ff2[NTOK*DFF];
__device__ float g_pool[B*DLLM];
__device__ float g_y1[B*768];
// split-bf16 operand scratch (raw bf16 bits in ushort)
__device__ unsigned short a_hi[NTOK*DFF], a_lo[NTOK*DFF];          // activations (A), reused
__device__ unsigned short w_hi[2u*DLLM*DFF], w_lo[2u*DLLM*DFF];    // weights (B, transposed), reused

__device__ __forceinline__ float siluf(float x) { return x / (1.f + expf(-x)); }

__device__ __forceinline__ void splitw(float v, unsigned short& h, unsigned short& l) {
    __nv_bfloat16 hb = __float2bfloat16(v);          // RN
    float hf = __bfloat162float(hb);
    __nv_bfloat16 lb = __float2bfloat16(v - hf);
    h = *reinterpret_cast<unsigned short*>(&hb);
    l = *reinterpret_cast<unsigned short*>(&lb);
}

// ======================= mma.sync plumbing =======================
__device__ __forceinline__ uint32_t smem_u32(const void* p) {
    uint32_t a;
    asm("{ .reg .u64 t; cvta.to.shared.u64 t, %1; cvt.u32.u64 %0, t; }" : "=r"(a) : "l"(p));
    return a;
}
#define LDSM4(R0,R1,R2,R3,addr) \
    asm volatile("ldmatrix.sync.aligned.m8n8.x4.shared.b16 {%0,%1,%2,%3}, [%4];" \
                 : "=r"(R0),"=r"(R1),"=r"(R2),"=r"(R3) : "r"(addr))
#define MMA(d, a, b) \
    asm volatile("mma.sync.aligned.m16n8k16.row.col.f32.bf16.bf16.f32 " \
        "{%0,%1,%2,%3},{%4,%5,%6,%7},{%8,%9},{%0,%1,%2,%3};" \
        : "+f"((d)[0]),"+f"((d)[1]),"+f"((d)[2]),"+f"((d)[3]) \
        : "r"((a)[0]),"r"((a)[1]),"r"((a)[2]),"r"((a)[3]),"r"((b)[0]),"r"((b)[1]))
#define CPA(dst, src) \
    asm volatile("cp.async.cg.shared.global [%0], [%1], 16;" :: "r"(dst), "l"(src))
#define CPA_COMMIT() asm volatile("cp.async.commit_group;" ::: "memory")

// Tile rows are 32 bf16 = 64B = four 16B chunks; XOR-swizzle chunks by row
// so ldmatrix 8-row phases hit all 32 banks (conflict-free).
__device__ __forceinline__ uint32_t swz(int r, int cChunk) {
    return (uint32_t)(r * 64 + (((cChunk) ^ ((r >> 1) & 3)) << 4));
}

// ====== pre-split bf16 tensor GEMM: C[M,N] (+)= A[M,K]@B[K,N], fp32 C ======
// Operands pre-split to hi/lo bf16; A row-major [M,K], B pre-TRANSPOSED [N,K].
// CTA 128x128, K-stage 32, 256 thr, 2-stage cp.async pipeline, 2 CTAs/SM.
// grid.z picks B slot (z*bStride) and C from {c0,c1,c2}.
// EPI: 0=store(+bias), 1=C+=acc.  orow = (r/rpbi)*rpbo + roff + r%rpbi
#define GSMEM 65536
template<int EPI>
__global__ __launch_bounds__(256, 2)
void gemm_bf16(int M, int N, int K,
               const unsigned short* __restrict__ Ah, const unsigned short* __restrict__ Al,
               const unsigned short* __restrict__ Bh, const unsigned short* __restrict__ Bl,
               size_t bStride, const float* __restrict__ bias,
               float* __restrict__ c0, float* __restrict__ c1, float* __restrict__ c2,
               int rpbi, int rpbo, int roff)
{
    const unsigned short* BmH = Bh + blockIdx.z * bStride;
    const unsigned short* BmL = Bl + blockIdx.z * bStride;
    float* C = (blockIdx.z == 0) ? c0 : ((blockIdx.z == 1) ? c1 : c2);

    extern __shared__ __align__(16) char sm[];   // 2 x (ah|al|bh|bl) 8KB each
    const uint32_t sb = smem_u32(sm);
    const int tid = threadIdx.x, lane = tid & 31, wid = tid >> 5;
    const int gm0 = blockIdx.x * 128, gn0 = blockIdx.y * 128;
    const int wm = (wid & 1) * 64, wn = (wid >> 1) * 32;

    float acc[4][4][4] = {};

    // producer: 2 threads per row, 2 x 16B chunks each (4 chunks/row of 64B)
    const int pr = tid >> 1;
    const int pc = (tid & 1) * 2;
    const uint32_t sw0 = swz(pr, pc), sw1 = swz(pr, pc + 1);
    const unsigned short* aHp = Ah + (size_t)(gm0 + pr) * K + pc * 8;
    const unsigned short* aLp = Al + (size_t)(gm0 + pr) * K + pc * 8;
    const unsigned short* bHp = BmH + (size_t)(gn0 + pr) * K + pc * 8;
    const unsigned short* bLp = BmL + (size_t)(gn0 + pr) * K + pc * 8;

    auto issue = [&](int s, int b) {
        const int k0 = s * 32;
        const uint32_t d = sb + b * 32768;
        CPA(d + sw0,         aHp + k0);
        CPA(d + sw1,         aHp + k0 + 8);
        CPA(d + 8192 + sw0,  aLp + k0);
        CPA(d + 8192 + sw1,  aLp + k0 + 8);
        CPA(d + 16384 + sw0, bHp + k0);
        CPA(d + 16384 + sw1, bHp + k0 + 8);
        CPA(d + 24576 + sw0, bLp + k0);
        CPA(d + 24576 + sw1, bLp + k0 + 8);
        CPA_COMMIT();
    };
    auto compute = [&](int b) {
        const uint32_t ahS = sb + b * 32768;
        const uint32_t alS = ahS + 8192, bhS = ahS + 16384, blS = ahS + 24576;
        #pragma unroll
        for (int half = 0; half < 2; half++) {
            uint32_t aH[4][4], aL[4][4], bH[4][2], bL[4][2];
            int cb = (half << 1) + (lane >> 4);
            #pragma unroll
            for (int mi = 0; mi < 4; mi++) {
                uint32_t off = swz(wm + mi * 16 + (lane & 15), cb);
                LDSM4(aH[mi][0], aH[mi][1], aH[mi][2], aH[mi][3], ahS + off);
                LDSM4(aL[mi][0], aL[mi][1], aL[mi][2], aL[mi][3], alS + off);
            }
            #pragma unroll
            for (int nh = 0; nh < 2; nh++) {
                uint32_t off = swz(wn + nh * 16 + (lane & 15), cb);
                uint32_t r0, r1, r2, r3;
                LDSM4(r0, r1, r2, r3, bhS + off);
                bH[2*nh][0] = r0; bH[2*nh][1] = r2; bH[2*nh+1][0] = r1; bH[2*nh+1][1] = r3;
                LDSM4(r0, r1, r2, r3, blS + off);
                bL[2*nh][0] = r0; bL[2*nh][1] = r2; bL[2*nh+1][0] = r1; bL[2*nh+1][1] = r3;
            }
            #pragma unroll
            for (int mi = 0; mi < 4; mi++)
                #pragma unroll
                for (int ni = 0; ni < 4; ni++) {
                    MMA(acc[mi][ni], aH[mi], bH[ni]);
                    MMA(acc[mi][ni], aH[mi], bL[ni]);
                    MMA(acc[mi][ni], aL[mi], bH[ni]);
                }
        }
    };

    const int nst = K / 32;
    issue(0, 0);
    for (int s = 0; s < nst; s++) {
        if (s + 1 < nst) {
            issue(s + 1, (s + 1) & 1);
            asm volatile("cp.async.wait_group 1;" ::: "memory");
        } else {
            asm volatile("cp.async.wait_group 0;" ::: "memory");
        }
        __syncthreads();
        compute(s & 1);
        __syncthreads();
    }

    // ---- epilogue ----
    #pragma unroll
    for (int mi = 0; mi < 4; mi++) {
        int rbase = gm0 + wm + mi * 16 + (lane >> 2);
        #pragma unroll
        for (int half = 0; half < 2; half++) {
            int r = rbase + half * 8;
            int orow = (r / rpbi) * rpbo + roff + (r % rpbi);
            float* Crow = C + (size_t)orow * N;
            #pragma unroll
            for (int ni = 0; ni < 4; ni++) {
                int col = gn0 + wn + ni * 8 + (lane & 3) * 2;
                float v0 = acc[mi][ni][half * 2 + 0];
                float v1 = acc[mi][ni][half * 2 + 1];
                float* d = Crow + col;
                if (EPI == 0) {
                    if (bias) { v0 += bias[col]; v1 += bias[col + 1]; }
                    d[0] = v0; d[1] = v1;
                } else {
                    d[0] += v0; d[1] += v1;
                }
            }
        }
    }
}

// ============== pre-split passes ==============
// Transpose+split weights: src [K,N] fp32 -> hi/lo [N,K] bf16 bits.
__global__ __launch_bounds__(256)
void tsplit_kernel(const float* __restrict__ s0, const float* __restrict__ s1,
                   const float* __restrict__ s2, int K, int N,
                   unsigned short* __restrict__ hi, unsigned short* __restrict__ lo,
                   size_t slotStride)
{
    const float* S = (blockIdx.z == 0) ? s0 : ((blockIdx.z == 1) ? s1 : s2);
    unsigned short* H = hi + blockIdx.z * slotStride;
    unsigned short* L = lo + blockIdx.z * slotStride;
    __shared__ float t[32][33];
    int k0 = blockIdx.x * 32, n0 = blockIdx.y * 32;
    int x = threadIdx.x & 31, y = threadIdx.x >> 5;
    #pragma unroll
    for (int j = 0; j < 32; j += 8)
        t[y + j][x] = S[(size_t)(k0 + y + j) * N + n0 + x];
    __syncthreads();
    #pragma unroll
    for (int j = 0; j < 32; j += 8) {
        float v = t[x][y + j];                       // (k = k0+x, n = n0+y+j)
        unsigned short hb, lb;
        splitw(v, hb, lb);
        size_t o = (size_t)(n0 + y + j) * K + k0 + x;
        H[o] = hb; L[o] = lb;
    }
}

// Elementwise split (text / vision inputs)
__global__ __launch_bounds__(256)
void split_kernel(const float* __restrict__ src, unsigned short* __restrict__ hi,
                  unsigned short* __restrict__ lo, int n4)
{
    int i = blockIdx.x * 256 + threadIdx.x;
    if (i >= n4) return;
    float4 v = ((const float4*)src)[i];
    ushort4 h, l;
    splitw(v.x, h.x, l.x); splitw(v.y, h.y, l.y);
    splitw(v.z, h.z, l.z); splitw(v.w, h.w, l.w);
    ((ushort4*)hi)[i] = h; ((ushort4*)lo)[i] = l;
}

// SwiGLU + split: a = split(silu(g) * u)
__global__ __launch_bounds__(256)
void swiglu_split_kernel(const float* __restrict__ g, const float* __restrict__ u,
                         unsigned short* __restrict__ hi, unsigned short* __restrict__ lo)
{
    int i = blockIdx.x * 256 + threadIdx.x;
    float4 gv = ((const float4*)g)[i];
    float4 uv = ((const float4*)u)[i];
    float4 v = make_float4(siluf(gv.x)*uv.x, siluf(gv.y)*uv.y,
                           siluf(gv.z)*uv.z, siluf(gv.w)*uv.w);
    ushort4 h, l;
    splitw(v.x, h.x, l.x); splitw(v.y, h.y, l.y);
    splitw(v.z, h.z, l.z); splitw(v.w, h.w, l.w);
    ((ushort4*)hi)[i] = h; ((ushort4*)lo)[i] = l;
}

// RMSNorm fused with split output
__global__ __launch_bounds__(256)
void rmsnorm_split_kernel(const float* __restrict__ in, const float* __restrict__ w,
                          unsigned short* __restrict__ hi, unsigned short* __restrict__ lo)
{
    size_t t = blockIdx.x;
    const float4* xp = (const float4*)(in + t * DLLM);
    __shared__ float red[8];
    float ss = 0.f;
    for (int i = threadIdx.x; i < DLLM / 4; i += 256) {
        float4 v = xp[i];
        ss += v.x*v.x + v.y*v.y + v.z*v.z + v.w*v.w;
    }
    #pragma unroll
    for (int o = 16; o; o >>= 1) ss += __shfl_xor_sync(0xffffffffu, ss, o);
    if ((threadIdx.x & 31) == 0) red[threadIdx.x >> 5] = ss;
    __syncthreads();
    if (threadIdx.x < 32) {
        float v = (threadIdx.x < 8) ? red[threadIdx.x] : 0.f;
        #pragma unroll
        for (int o = 4; o; o >>= 1) v += __shfl_xor_sync(0xffffffffu, v, o);
        if (threadIdx.x == 0) red[0] = v;
    }
    __syncthreads();
    float r = rsqrtf(red[0] / (float)DLLM + EPSRMS);
    const float4* wp = (const float4*)w;
    ushort4* hp = (ushort4*)(hi + t * DLLM);
    ushort4* lp = (ushort4*)(lo + t * DLLM);
    for (int i = threadIdx.x; i < DLLM / 4; i += 256) {
        float4 v = xp[i], wv = wp[i];
        float4 y = make_float4(v.x*r*wv.x, v.y*r*wv.y, v.z*r*wv.z, v.w*r*wv.w);
        ushort4 h, l;
        splitw(y.x, h.x, l.x); splitw(y.y, h.y, l.y);
        splitw(y.z, h.z, l.z); splitw(y.w, h.w, l.w);
        hp[i] = h; lp[i] = l;
    }
}

// ======================= aux kernels =======================
__global__ __launch_bounds__(256)
void embed_kernel(const int* __restrict__ ids, const float* __restrict__ table,
                  float* __restrict__ h)
{
    int t = blockIdx.x;
    int b = t >> 7, p = t & 127;
    int id = ids[t];
    const float4* src = (const float4*)(table + (size_t)id * DLLM);
    float4* dst = (float4*)(h + ((size_t)b * SEQ + p) * DLLM);
    for (int i = threadIdx.x; i < DLLM / 4; i += 256) dst[i] = src[i];
}

__global__ __launch_bounds__(256)
void rmsnorm_kernel(const float* __restrict__ in, const float* __restrict__ w,
                    float* __restrict__ out)
{
    size_t t = blockIdx.x;
    const float4* xp = (const float4*)(in + t * DLLM);
    __shared__ float red[8];
    float ss = 0.f;
    for (int i = threadIdx.x; i < DLLM / 4; i += 256) {
        float4 v = xp[i];
        ss += v.x*v.x + v.y*v.y + v.z*v.z + v.w*v.w;
    }
    #pragma unroll
    for (int o = 16; o; o >>= 1) ss += __shfl_xor_sync(0xffffffffu, ss, o);
    if ((threadIdx.x & 31) == 0) red[threadIdx.x >> 5] = ss;
    __syncthreads();
    if (threadIdx.x < 32) {
        float v = (threadIdx.x < 8) ? red[threadIdx.x] : 0.f;
        #pragma unroll
        for (int o = 4; o; o >>= 1) v += __shfl_xor_sync(0xffffffffu, v, o);
        if (threadIdx.x == 0) red[0] = v;
    }
    __syncthreads();
    float r = rsqrtf(red[0] / (float)DLLM + EPSRMS);
    const float4* wp = (const float4*)w;
    float4* op = (float4*)(out + t * DLLM);
    for (int i = threadIdx.x; i < DLLM / 4; i += 256) {
        float4 v = xp[i], wv = wp[i];
        op[i] = make_float4(v.x*r*wv.x, v.y*r*wv.y, v.z*r*wv.z, v.w*r*wv.w);
    }
}

__global__ __launch_bounds__(256)
void rope_kernel(float* __restrict__ q, float* __restrict__ k)
{
    int t = blockIdx.x;
    int pos = t & (SEQ - 1);
    const float LOG_THETA = 9.210340371976184f;
    for (int it = 0; it < 8; it++) {
        int p = threadIdx.x + it * 256;
        int hh = p >> 6, j = p & 63;
        float inv_freq = expf(-(float)j * (LOG_THETA / 64.f));
        float ang = (float)pos * inv_freq;
        float c = cosf(ang), s = sinf(ang);
        size_t base = (size_t)t * DLLM + hh * HD + j;
        float x1 = q[base], x2 = q[base + 64];
        q[base]      = x1 * c - x2 * s;
        q[base + 64] = x2 * c + x1 * s;
        x1 = k[base]; x2 = k[base + 64];
        k[base]      = x1 * c - x2 * s;
        k[base + 64] = x2 * c + x1 * s;
    }
}

__global__ __launch_bounds__(256)
void score_kernel(const float* __restrict__ Q, const float* __restrict__ K,
                  float* __restrict__ Sc)
{
    int bh = blockIdx.z;
    int b = bh >> 5, hh = bh & 31;
    int qi0 = blockIdx.y * 64, kj0 = blockIdx.x * 64;
    __shared__ float As[16][64];
    __shared__ float Bs[16][64];
    int tid = threadIdx.x;
    int tx = tid & 15, ty = tid >> 4;
    float acc[4][4] = {};
    const float* Qb = Q + ((size_t)b * SEQ + qi0) * DLLM + hh * HD;
    const float* Kb = K + ((size_t)b * SEQ + kj0) * DLLM + hh * HD;
    int r  = tid >> 2;
    int c4 = (tid & 3) * 4;
    for (int k0 = 0; k0 < HD; k0 += 16) {
        float4 qa = *(const float4*)(Qb + (size_t)r * DLLM + k0 + c4);
        As[c4+0][r] = qa.x; As[c4+1][r] = qa.y; As[c4+2][r] = qa.z; As[c4+3][r] = qa.w;
        float4 ka = *(const float4*)(Kb + (size_t)r * DLLM + k0 + c4);
        Bs[c4+0][r] = ka.x; Bs[c4+1][r] = ka.y; Bs[c4+2][r] = ka.z; Bs[c4+3][r] = ka.w;
        __syncthreads();
        #pragma unroll
        for (int kk = 0; kk < 16; kk++) {
            float a[4], bb[4];
            *(float4*)a  = *(const float4*)&As[kk][ty * 4];
            *(float4*)bb = *(const float4*)&Bs[kk][tx * 4];
            #pragma unroll
            for (int i = 0; i < 4; i++)
                #pragma unroll
                for (int j = 0; j < 4; j++)
                    acc[i][j] = fmaf(a[i], bb[j], acc[i][j]);
        }
        __syncthreads();
    }
    const float scale = 0.08838834764831845f;
    #pragma unroll
    for (int i = 0; i < 4; i++) {
        int qi = qi0 + ty * 4 + i;
        float* dst = Sc + ((size_t)bh * SEQ + qi) * SEQ + kj0 + tx * 4;
        #pragma unroll
        for (int j = 0; j < 4; j++) {
            int kj = kj0 + tx * 4 + j;
            dst[j] = (kj > qi) ? -1e30f : acc[i][j] * scale;
        }
    }
}

__global__ __launch_bounds__(256)
void softmax_kernel(float* __restrict__ Sc)
{
    float* p = Sc + (size_t)blockIdx.x * SEQ;
    int tid = threadIdx.x;
    __shared__ float redm[8], reds[8];
    float v = p[tid];
    float m = v;
    #pragma unroll
    for (int o = 16; o; o >>= 1) m = fmaxf(m, __shfl_xor_sync(0xffffffffu, m, o));
    if ((tid & 31) == 0) redm[tid >> 5] = m;
    __syncthreads();
    if (tid < 32) {
        float x = (tid < 8) ? redm[tid] : -3.4e38f;
        #pragma unroll
        for (int o = 4; o; o >>= 1) x = fmaxf(x, __shfl_xor_sync(0xffffffffu, x, o));
        if (tid == 0) redm[0] = x;
    }
    __syncthreads();
    m = redm[0];
    float e = expf(v - m);
    float s = e;
    #pragma unroll
    for (int o = 16; o; o >>= 1) s += __shfl_xor_sync(0xffffffffu, s, o);
    if ((tid & 31) == 0) reds[tid >> 5] = s;
    __syncthreads();
    if (tid < 32) {
        float x = (tid < 8) ? reds[tid] : 0.f;
        #pragma unroll
        for (int o = 4; o; o >>= 1) x += __shfl_xor_sync(0xffffffffu, x, o);
        if (tid == 0) reds[0] = x;
    }
    __syncthreads();
    p[tid] = e / reds[0];
}

// attn @ V; epilogue emits split-bf16 A operand for the Wo GEMM
__global__ __launch_bounds__(256)
void av_kernel(const float* __restrict__ P, const float* __restrict__ V,
               unsigned short* __restrict__ Oh, unsigned short* __restrict__ Ol)
{
    int bh = blockIdx.y;
    int b = bh >> 5, hh = bh & 31;
    int qi0 = blockIdx.x * 64;
    __shared__ float Ps[16][64];
    __shared__ float Vs[16][128];
    int tid = threadIdx.x;
    int tx = tid & 31, ty = tid >> 5;
    float acc[8][4] = {};
    const float* Pb = P + ((size_t)bh * SEQ + qi0) * SEQ;
    const float* Vb = V + (size_t)b * SEQ * DLLM + hh * HD;
    int pq = tid >> 2, pk4 = (tid & 3) * 4;
    int vk = tid >> 4, vd8 = (tid & 15) * 8;
    for (int k0 = 0; k0 < SEQ; k0 += 16) {
        float4 pv = *(const float4*)(Pb + (size_t)pq * SEQ + k0 + pk4);
        Ps[pk4+0][pq] = pv.x; Ps[pk4+1][pq] = pv.y; Ps[pk4+2][pq] = pv.z; Ps[pk4+3][pq] = pv.w;
        const float* src = Vb + (size_t)(k0 + vk) * DLLM + vd8;
        *(float4*)&Vs[vk][vd8]     = *(const float4*)(src);
        *(float4*)&Vs[vk][vd8 + 4] = *(const float4*)(src + 4);
        __syncthreads();
        #pragma unroll
        for (int kk = 0; kk < 16; kk++) {
            float a[8], bb[4];
            *(float4*)(a)     = *(const float4*)&Ps[kk][ty * 8];
            *(float4*)(a + 4) = *(const float4*)&Ps[kk][ty * 8 + 4];
            *(float4*)bb      = *(const float4*)&Vs[kk][tx * 4];
            #pragma unroll
            for (int i = 0; i < 8; i++)
                #pragma unroll
                for (int j = 0; j < 4; j++)
                    acc[i][j] = fmaf(a[i], bb[j], acc[i][j]);
        }
        __syncthreads();
    }
    #pragma unroll
    for (int i = 0; i < 8; i++) {
        int qi = qi0 + ty * 8 + i;
        size_t o = ((size_t)b * SEQ + qi) * DLLM + hh * HD + tx * 4;
        ushort4 h, l;
        splitw(acc[i][0], h.x, l.x); splitw(acc[i][1], h.y, l.y);
        splitw(acc[i][2], h.z, l.z); splitw(acc[i][3], h.w, l.w);
        *(ushort4*)(Oh + o) = h;
        *(ushort4*)(Ol + o) = l;
    }
}

__global__ __launch_bounds__(256)
void pool_kernel(const float* __restrict__ x, float* __restrict__ pooled)
{
    int b = blockIdx.x;
    int d = blockIdx.y * 256 + threadIdx.x;
    float s = 0.f;
    const float* base = x + (size_t)b * SEQ * DLLM + d;
    for (int t = 0; t < SEQ; t++) s += base[(size_t)t * DLLM];
    pooled[(size_t)b * DLLM + d] = s * (1.f / SEQ);
}

__global__ __launch_bounds__(256)
void out1_kernel(const float* __restrict__ pooled, const float* __restrict__ W,
                 const float* __restrict__ bias, float* __restrict__ y1)
{
    int b = blockIdx.x;
    int n = blockIdx.y * 256 + threadIdx.x;
    const float* pv = pooled + (size_t)b * DLLM;
    float acc = bias[n];
    for (int k = 0; k < DLLM; k++)
        acc = fmaf(pv[k], W[(size_t)k * 768 + n], acc);
    y1[(size_t)b * 768 + n] = acc;
}

__global__ __launch_bounds__(256)
void out2_kernel(const float* __restrict__ y1, const float* __restrict__ W2,
                 const float* __restrict__ b2, float* __restrict__ out)
{
    int b = blockIdx.x;
    int tid = threadIdx.x;
    __shared__ float red[8];
    float s = 0.f;
    for (int j = tid; j < 768; j += 256) s += y1[(size_t)b * 768 + j] * W2[j];
    #pragma unroll
    for (int o = 16; o; o >>= 1) s += __shfl_xor_sync(0xffffffffu, s, o);
    if ((tid & 31) == 0) red[tid >> 5] = s;
    __syncthreads();
    if (tid < 32) {
        float x = (tid < 8) ? red[tid] : 0.f;
        #pragma unroll
        for (int o = 4; o; o >>= 1) x += __shfl_xor_sync(0xffffffffu, x, o);
        if (tid == 0) out[b] = x + b2[0];
    }
}

// ======================= host orchestration =======================
extern "C" void kernel_launch(void* const* d_in, const int* in_sizes, int n_in,
                              void* d_out, int out_size)
{
    const float* text    = (const float*)d_in[0];
    const float* vision  = (const float*)d_in[1];
    const int*   prompt  = (const int*)  d_in[2];
    const float* in_W    = (const float*)d_in[3];
    const float* in_b    = (const float*)d_in[4];
    const float* table   = (const float*)d_in[5];
    const float* Wq      = (const float*)d_in[6];
    const float* Wk      = (const float*)d_in[7];
    const float* Wv      = (const float*)d_in[8];
    const float* Wo      = (const float*)d_in[9];
    const float* ln1     = (const float*)d_in[10];
    const float* ln2     = (const float*)d_in[11];
    const float* Wg      = (const float*)d_in[12];
    const float* Wu      = (const float*)d_in[13];
    const float* Wd      = (const float*)d_in[14];
    const float* final_w = (const float*)d_in[15];
    const float* out1W   = (const float*)d_in[16];
    const float* out1b   = (const float*)d_in[17];
    const float* out2W   = (const float*)d_in[18];
    const float* out2b   = (const float*)d_in[19];
    float* out = (float*)d_out;

    float *h, *q, *k, *v, *sc, *ff, *ff2, *pooled, *y1;
    unsigned short *ah, *al, *wh, *wl;
    cudaGetSymbolAddress((void**)&h,   g_h);
    cudaGetSymbolAddress((void**)&q,   g_q);
    cudaGetSymbolAddress((void**)&k,   g_k);
    cudaGetSymbolAddress((void**)&v,   g_v);
    cudaGetSymbolAddress((void**)&sc,  g_sc);
    cudaGetSymbolAddress((void**)&ff,  g_ff);
    cudaGetSymbolAddress((void**)&ff2, g_ff2);
    cudaGetSymbolAddress((void**)&pooled, g_pool);
    cudaGetSymbolAddress((void**)&y1,  g_y1);
    cudaGetSymbolAddress((void**)&ah,  a_hi);
    cudaGetSymbolAddress((void**)&al,  a_lo);
    cudaGetSymbolAddress((void**)&wh,  w_hi);
    cudaGetSymbolAddress((void**)&wl,  w_lo);

    cudaFuncSetAttribute(gemm_bf16<0>, cudaFuncAttributeMaxDynamicSharedMemorySize, GSMEM);
    cudaFuncSetAttribute(gemm_bf16<1>, cudaFuncAttributeMaxDynamicSharedMemorySize, GSMEM);

    // ---- inputs into concatenated h: [prompt(128) | text(64) | vision(64)] ----
    embed_kernel<<<B * S_P, 256>>>(prompt, table, h);
    tsplit_kernel<<<dim3(DMODEL/32, DLLM/32, 1), 256>>>(in_W, in_W, in_W, DMODEL, DLLM, wh, wl, 0);
    split_kernel<<<(B*S_T*DMODEL/4 + 255)/256, 256>>>(text, ah, al, B*S_T*DMODEL/4);
    gemm_bf16<0><<<dim3((B*S_T)/128, DLLM/128, 1), 256, GSMEM>>>(
        B*S_T, DLLM, DMODEL, ah, al, wh, wl, 0, in_b, h, h, h, S_T, SEQ, S_P);
    split_kernel<<<(B*S_V*DMODEL/4 + 255)/256, 256>>>(vision, ah, al, B*S_V*DMODEL/4);
    gemm_bf16<0><<<dim3((B*S_V)/128, DLLM/128, 1), 256, GSMEM>>>(
        B*S_V, DLLM, DMODEL, ah, al, wh, wl, 0, in_b, h, h, h, S_V, SEQ, S_P + S_T);

    for (int l = 0; l < NLAYER; l++) {
        const float* wq = Wq + (size_t)l * DLLM * DLLM;
        const float* wk = Wk + (size_t)l * DLLM * DLLM;
        const float* wv = Wv + (size_t)l * DLLM * DLLM;
        const float* wo = Wo + (size_t)l * DLLM * DLLM;
        const float* wg = Wg + (size_t)l * DLLM * DFF;
        const float* wu = Wu + (size_t)l * DLLM * DFF;
        const float* wd = Wd + (size_t)l * DFF * DLLM;
        const float* l1 = ln1 + (size_t)l * DLLM;
        const float* l2 = ln2 + (size_t)l * DLLM;

        // --- attention block ---
        rmsnorm_split_kernel<<<NTOK, 256>>>(h, l1, ah, al);
        tsplit_kernel<<<dim3(DLLM/32, DLLM/32, 3), 256>>>(wq, wk, wv, DLLM, DLLM,
                                                          wh, wl, (size_t)DLLM*DLLM);
        gemm_bf16<0><<<dim3(NTOK/128, DLLM/128, 3), 256, GSMEM>>>(
            NTOK, DLLM, DLLM, ah, al, wh, wl, (size_t)DLLM*DLLM, nullptr,
            q, k, v, NTOK, NTOK, 0);
        rope_kernel<<<NTOK, 256>>>(q, k);
        score_kernel<<<dim3(SEQ/64, SEQ/64, B*NH), 256>>>(q, k, sc);
        softmax_kernel<<<B*NH*SEQ, 256>>>(sc);
        av_kernel<<<dim3(SEQ/64, B*NH), 256>>>(sc, v, ah, al);
        tsplit_kernel<<<dim3(DLLM/32, DLLM/32, 1), 256>>>(wo, wo, wo, DLLM, DLLM, wh, wl, 0);
        gemm_bf16<1><<<dim3(NTOK/128, DLLM/128, 1), 256, GSMEM>>>(
            NTOK, DLLM, DLLM, ah, al, wh, wl, 0, nullptr, h, h, h, NTOK, NTOK, 0);

        // --- FFN block ---
        rmsnorm_split_kernel<<<NTOK, 256>>>(h, l2, ah, al);
        tsplit_kernel<<<dim3(DLLM/32, DFF/32, 2), 256>>>(wg, wu, wu, DLLM, DFF,
                                                         wh, wl, (size_t)DLLM*DFF);
        gemm_bf16<0><<<dim3(NTOK/128, DFF/128, 2), 256, GSMEM>>>(
            NTOK, DFF, DLLM, ah, al, wh, wl, (size_t)DLLM*DFF, nullptr,
            ff, ff2, ff2, NTOK, NTOK, 0);
        swiglu_split_kernel<<<(NTOK*(DFF/4))/256, 256>>>(ff, ff2, ah, al);
        tsplit_kernel<<<dim3(DFF/32, DLLM/32, 1), 256>>>(wd, wd, wd, DFF, DLLM, wh, wl, 0);
        gemm_bf16<1><<<dim3(NTOK/128, DLLM/128, 1), 256, GSMEM>>>(
            NTOK, DLLM, DFF, ah, al, wh, wl, 0, nullptr, h, h, h, NTOK, NTOK, 0);
    }

    rmsnorm_kernel<<<NTOK, 256>>>(h, final_w, q);   // q free: fp32 normed out
    pool_kernel<<<dim3(B, DLLM/256), 256>>>(q, pooled);
    out1_kernel<<<dim3(B, 768/256), 256>>>(pooled, out1W, out1b, y1);
    out2_kernel<<<B, 256>>>(y1, out2W, out2b, out);
}

// round 15
// speedup vs baseline: 1.4886x; 1.0121x over previous
#include <cuda_runtime.h>
#include <cuda_bf16.h>
#include <math.h>
#include <stdint.h>

#define B      8
#define S_P    128
#define S_T    64
#define S_V    64
#define SEQ    256
#define DMODEL 768
#define DLLM   4096
#define NH     32
#define HD     128
#define DFF    11008
#define NLAYER 2
#define NTOK   (B*SEQ)
#define EPSRMS 1e-5f

__device__ float g_h  [NTOK*DLLM];
__device__ float g_q  [NTOK*DLLM];
__device__ float g_k  [NTOK*DLLM];
__device__ float g_v  [NTOK*DLLM];
__device__ float g_sc [B*NH*SEQ*SEQ];
__device__ float g_ff [NTOK*DFF];
__device__ float g_ff2[NTOK*DFF];
__device__ float g_pool[B*DLLM];
__device__ float g_y1[B*768];
// split-bf16 operand scratch (raw bf16 bits in ushort)
__device__ unsigned short a_hi[NTOK*DFF], a_lo[NTOK*DFF];          // activations (A), reused
__device__ unsigned short w_hi[2u*DLLM*DFF], w_lo[2u*DLLM*DFF];    // weights (B, transposed), reused

__device__ __forceinline__ float siluf(float x) { return x / (1.f + expf(-x)); }

__device__ __forceinline__ void splitw(float v, unsigned short& h, unsigned short& l) {
    __nv_bfloat16 hb = __float2bfloat16(v);          // RN
    float hf = __bfloat162float(hb);
    __nv_bfloat16 lb = __float2bfloat16(v - hf);
    h = *reinterpret_cast<unsigned short*>(&hb);
    l = *reinterpret_cast<unsigned short*>(&lb);
}

// ======================= mma.sync plumbing =======================
__device__ __forceinline__ uint32_t smem_u32(const void* p) {
    uint32_t a;
    asm("{ .reg .u64 t; cvta.to.shared.u64 t, %1; cvt.u32.u64 %0, t; }" : "=r"(a) : "l"(p));
    return a;
}
#define LDSM4(R0,R1,R2,R3,addr) \
    asm volatile("ldmatrix.sync.aligned.m8n8.x4.shared.b16 {%0,%1,%2,%3}, [%4];" \
                 : "=r"(R0),"=r"(R1),"=r"(R2),"=r"(R3) : "r"(addr))
#define MMA(d, a, b) \
    asm volatile("mma.sync.aligned.m16n8k16.row.col.f32.bf16.bf16.f32 " \
        "{%0,%1,%2,%3},{%4,%5,%6,%7},{%8,%9},{%0,%1,%2,%3};" \
        : "+f"((d)[0]),"+f"((d)[1]),"+f"((d)[2]),"+f"((d)[3]) \
        : "r"((a)[0]),"r"((a)[1]),"r"((a)[2]),"r"((a)[3]),"r"((b)[0]),"r"((b)[1]))
#define CPA(dst, src) \
    asm volatile("cp.async.cg.shared.global [%0], [%1], 16;" :: "r"(dst), "l"(src))
#define CPA_COMMIT() asm volatile("cp.async.commit_group;" ::: "memory")

// Tile rows are 32 bf16 = 64B = four 16B chunks; XOR-swizzle chunks by row
// so ldmatrix 8-row phases hit all 32 banks (conflict-free).
__device__ __forceinline__ uint32_t swz(int r, int cChunk) {
    return (uint32_t)(r * 64 + (((cChunk) ^ ((r >> 1) & 3)) << 4));
}

// ====== pre-split bf16 tensor GEMM: C[M,N] (+)= A[M,K]@B[K,N], fp32 C ======
// Operands pre-split to hi/lo bf16; A row-major [M,K], B pre-TRANSPOSED [N,K].
// CTA 128x128, K-stage 32, 256 thr, 3-stage cp.async ring, ONE sync/stage,
// 2 CTAs/SM. grid.z picks B slot (z*bStride) and C from {c0,c1,c2}.
// EPI: 0=store(+bias), 1=C+=acc.  orow = (r/rpbi)*rpbo + roff + r%rpbi
#define GSMEM 98304
template<int EPI>
__global__ __launch_bounds__(256, 2)
void gemm_bf16(int M, int N, int K,
               const unsigned short* __restrict__ Ah, const unsigned short* __restrict__ Al,
               const unsigned short* __restrict__ Bh, const unsigned short* __restrict__ Bl,
               size_t bStride, const float* __restrict__ bias,
               float* __restrict__ c0, float* __restrict__ c1, float* __restrict__ c2,
               int rpbi, int rpbo, int roff)
{
    const unsigned short* BmH = Bh + blockIdx.z * bStride;
    const unsigned short* BmL = Bl + blockIdx.z * bStride;
    float* C = (blockIdx.z == 0) ? c0 : ((blockIdx.z == 1) ? c1 : c2);

    extern __shared__ __align__(16) char sm[];   // 3 x (ah|al|bh|bl) 8KB each
    const uint32_t sb = smem_u32(sm);
    const int tid = threadIdx.x, lane = tid & 31, wid = tid >> 5;
    const int gm0 = blockIdx.x * 128, gn0 = blockIdx.y * 128;
    const int wm = (wid & 1) * 64, wn = (wid >> 1) * 32;

    float acc[4][4][4] = {};

    // producer: 2 threads per row, 2 x 16B chunks each (4 chunks/row of 64B)
    const int pr = tid >> 1;
    const int pc = (tid & 1) * 2;
    const uint32_t sw0 = swz(pr, pc), sw1 = swz(pr, pc + 1);
    const unsigned short* aHp = Ah + (size_t)(gm0 + pr) * K + pc * 8;
    const unsigned short* aLp = Al + (size_t)(gm0 + pr) * K + pc * 8;
    const unsigned short* bHp = BmH + (size_t)(gn0 + pr) * K + pc * 8;
    const unsigned short* bLp = BmL + (size_t)(gn0 + pr) * K + pc * 8;

    auto issue = [&](int s) {
        const int k0 = s * 32;
        const uint32_t d = sb + (s % 3) * 32768;
        CPA(d + sw0,         aHp + k0);
        CPA(d + sw1,         aHp + k0 + 8);
        CPA(d + 8192 + sw0,  aLp + k0);
        CPA(d + 8192 + sw1,  aLp + k0 + 8);
        CPA(d + 16384 + sw0, bHp + k0);
        CPA(d + 16384 + sw1, bHp + k0 + 8);
        CPA(d + 24576 + sw0, bLp + k0);
        CPA(d + 24576 + sw1, bLp + k0 + 8);
        CPA_COMMIT();
    };
    auto compute = [&](int s) {
        const uint32_t ahS = sb + (s % 3) * 32768;
        const uint32_t alS = ahS + 8192, bhS = ahS + 16384, blS = ahS + 24576;
        #pragma unroll
        for (int half = 0; half < 2; half++) {
            uint32_t aH[4][4], aL[4][4], bH[4][2], bL[4][2];
            int cb = (half << 1) + (lane >> 4);
            #pragma unroll
            for (int mi = 0; mi < 4; mi++) {
                uint32_t off = swz(wm + mi * 16 + (lane & 15), cb);
                LDSM4(aH[mi][0], aH[mi][1], aH[mi][2], aH[mi][3], ahS + off);
                LDSM4(aL[mi][0], aL[mi][1], aL[mi][2], aL[mi][3], alS + off);
            }
            #pragma unroll
            for (int nh = 0; nh < 2; nh++) {
                uint32_t off = swz(wn + nh * 16 + (lane & 15), cb);
                uint32_t r0, r1, r2, r3;
                LDSM4(r0, r1, r2, r3, bhS + off);
                bH[2*nh][0] = r0; bH[2*nh][1] = r2; bH[2*nh+1][0] = r1; bH[2*nh+1][1] = r3;
                LDSM4(r0, r1, r2, r3, blS + off);
                bL[2*nh][0] = r0; bL[2*nh][1] = r2; bL[2*nh+1][0] = r1; bL[2*nh+1][1] = r3;
            }
            #pragma unroll
            for (int mi = 0; mi < 4; mi++)
                #pragma unroll
                for (int ni = 0; ni < 4; ni++) {
                    MMA(acc[mi][ni], aH[mi], bH[ni]);
                    MMA(acc[mi][ni], aH[mi], bL[ni]);
                    MMA(acc[mi][ni], aL[mi], bH[ni]);
                }
        }
    };

    const int nst = K / 32;
    issue(0);
    issue(1);
    for (int s = 0; s < nst; s++) {
        // group s committed; pending <= {s, s+1}. Last stage needs full drain.
        if (s + 1 < nst) { asm volatile("cp.async.wait_group 1;" ::: "memory"); }
        else             { asm volatile("cp.async.wait_group 0;" ::: "memory"); }
        __syncthreads();   // data of stage s visible to all; WAR for buf (s+2)%3
        if (s + 2 < nst) issue(s + 2);
        compute(s);
    }

    // ---- epilogue ----
    #pragma unroll
    for (int mi = 0; mi < 4; mi++) {
        int rbase = gm0 + wm + mi * 16 + (lane >> 2);
        #pragma unroll
        for (int half = 0; half < 2; half++) {
            int r = rbase + half * 8;
            int orow = (r / rpbi) * rpbo + roff + (r % rpbi);
            float* Crow = C + (size_t)orow * N;
            #pragma unroll
            for (int ni = 0; ni < 4; ni++) {
                int col = gn0 + wn + ni * 8 + (lane & 3) * 2;
                float v0 = acc[mi][ni][half * 2 + 0];
                float v1 = acc[mi][ni][half * 2 + 1];
                float* d = Crow + col;
                if (EPI == 0) {
                    if (bias) { v0 += bias[col]; v1 += bias[col + 1]; }
                    d[0] = v0; d[1] = v1;
                } else {
                    d[0] += v0; d[1] += v1;
                }
            }
        }
    }
}

// ============== pre-split passes ==============
// Transpose+split weights: src [K,N] fp32 -> hi/lo [N,K] bf16 bits.
__global__ __launch_bounds__(256)
void tsplit_kernel(const float* __restrict__ s0, const float* __restrict__ s1,
                   const float* __restrict__ s2, int K, int N,
                   unsigned short* __restrict__ hi, unsigned short* __restrict__ lo,
                   size_t slotStride)
{
    const float* S = (blockIdx.z == 0) ? s0 : ((blockIdx.z == 1) ? s1 : s2);
    unsigned short* H = hi + blockIdx.z * slotStride;
    unsigned short* L = lo + blockIdx.z * slotStride;
    __shared__ float t[32][33];
    int k0 = blockIdx.x * 32, n0 = blockIdx.y * 32;
    int x = threadIdx.x & 31, y = threadIdx.x >> 5;
    #pragma unroll
    for (int j = 0; j < 32; j += 8)
        t[y + j][x] = S[(size_t)(k0 + y + j) * N + n0 + x];
    __syncthreads();
    #pragma unroll
    for (int j = 0; j < 32; j += 8) {
        float v = t[x][y + j];                       // (k = k0+x, n = n0+y+j)
        unsigned short hb, lb;
        splitw(v, hb, lb);
        size_t o = (size_t)(n0 + y + j) * K + k0 + x;
        H[o] = hb; L[o] = lb;
    }
}

// Elementwise split (text / vision inputs)
__global__ __launch_bounds__(256)
void split_kernel(const float* __restrict__ src, unsigned short* __restrict__ hi,
                  unsigned short* __restrict__ lo, int n4)
{
    int i = blockIdx.x * 256 + threadIdx.x;
    if (i >= n4) return;
    float4 v = ((const float4*)src)[i];
    ushort4 h, l;
    splitw(v.x, h.x, l.x); splitw(v.y, h.y, l.y);
    splitw(v.z, h.z, l.z); splitw(v.w, h.w, l.w);
    ((ushort4*)hi)[i] = h; ((ushort4*)lo)[i] = l;
}

// SwiGLU + split: a = split(silu(g) * u)
__global__ __launch_bounds__(256)
void swiglu_split_kernel(const float* __restrict__ g, const float* __restrict__ u,
                         unsigned short* __restrict__ hi, unsigned short* __restrict__ lo)
{
    int i = blockIdx.x * 256 + threadIdx.x;
    float4 gv = ((const float4*)g)[i];
    float4 uv = ((const float4*)u)[i];
    float4 v = make_float4(siluf(gv.x)*uv.x, siluf(gv.y)*uv.y,
                           siluf(gv.z)*uv.z, siluf(gv.w)*uv.w);
    ushort4 h, l;
    splitw(v.x, h.x, l.x); splitw(v.y, h.y, l.y);
    splitw(v.z, h.z, l.z); splitw(v.w, h.w, l.w);
    ((ushort4*)hi)[i] = h; ((ushort4*)lo)[i] = l;
}

// RMSNorm fused with split output
__global__ __launch_bounds__(256)
void rmsnorm_split_kernel(const float* __restrict__ in, const float* __restrict__ w,
                          unsigned short* __restrict__ hi, unsigned short* __restrict__ lo)
{
    size_t t = blockIdx.x;
    const float4* xp = (const float4*)(in + t * DLLM);
    __shared__ float red[8];
    float ss = 0.f;
    for (int i = threadIdx.x; i < DLLM / 4; i += 256) {
        float4 v = xp[i];
        ss += v.x*v.x + v.y*v.y + v.z*v.z + v.w*v.w;
    }
    #pragma unroll
    for (int o = 16; o; o >>= 1) ss += __shfl_xor_sync(0xffffffffu, ss, o);
    if ((threadIdx.x & 31) == 0) red[threadIdx.x >> 5] = ss;
    __syncthreads();
    if (threadIdx.x < 32) {
        float v = (threadIdx.x < 8) ? red[threadIdx.x] : 0.f;
        #pragma unroll
        for (int o = 4; o; o >>= 1) v += __shfl_xor_sync(0xffffffffu, v, o);
        if (threadIdx.x == 0) red[0] = v;
    }
    __syncthreads();
    float r = rsqrtf(red[0] / (float)DLLM + EPSRMS);
    const float4* wp = (const float4*)w;
    ushort4* hp = (ushort4*)(hi + t * DLLM);
    ushort4* lp = (ushort4*)(lo + t * DLLM);
    for (int i = threadIdx.x; i < DLLM / 4; i += 256) {
        float4 v = xp[i], wv = wp[i];
        float4 y = make_float4(v.x*r*wv.x, v.y*r*wv.y, v.z*r*wv.z, v.w*r*wv.w);
        ushort4 h, l;
        splitw(y.x, h.x, l.x); splitw(y.y, h.y, l.y);
        splitw(y.z, h.z, l.z); splitw(y.w, h.w, l.w);
        hp[i] = h; lp[i] = l;
    }
}

// ======================= aux kernels =======================
__global__ __launch_bounds__(256)
void embed_kernel(const int* __restrict__ ids, const float* __restrict__ table,
                  float* __restrict__ h)
{
    int t = blockIdx.x;
    int b = t >> 7, p = t & 127;
    int id = ids[t];
    const float4* src = (const float4*)(table + (size_t)id * DLLM);
    float4* dst = (float4*)(h + ((size_t)b * SEQ + p) * DLLM);
    for (int i = threadIdx.x; i < DLLM / 4; i += 256) dst[i] = src[i];
}

__global__ __launch_bounds__(256)
void rmsnorm_kernel(const float* __restrict__ in, const float* __restrict__ w,
                    float* __restrict__ out)
{
    size_t t = blockIdx.x;
    const float4* xp = (const float4*)(in + t * DLLM);
    __shared__ float red[8];
    float ss = 0.f;
    for (int i = threadIdx.x; i < DLLM / 4; i += 256) {
        float4 v = xp[i];
        ss += v.x*v.x + v.y*v.y + v.z*v.z + v.w*v.w;
    }
    #pragma unroll
    for (int o = 16; o; o >>= 1) ss += __shfl_xor_sync(0xffffffffu, ss, o);
    if ((threadIdx.x & 31) == 0) red[threadIdx.x >> 5] = ss;
    __syncthreads();
    if (threadIdx.x < 32) {
        float v = (threadIdx.x < 8) ? red[threadIdx.x] : 0.f;
        #pragma unroll
        for (int o = 4; o; o >>= 1) v += __shfl_xor_sync(0xffffffffu, v, o);
        if (threadIdx.x == 0) red[0] = v;
    }
    __syncthreads();
    float r = rsqrtf(red[0] / (float)DLLM + EPSRMS);
    const float4* wp = (const float4*)w;
    float4* op = (float4*)(out + t * DLLM);
    for (int i = threadIdx.x; i < DLLM / 4; i += 256) {
        float4 v = xp[i], wv = wp[i];
        op[i] = make_float4(v.x*r*wv.x, v.y*r*wv.y, v.z*r*wv.z, v.w*r*wv.w);
    }
}

__global__ __launch_bounds__(256)
void rope_kernel(float* __restrict__ q, float* __restrict__ k)
{
    int t = blockIdx.x;
    int pos = t & (SEQ - 1);
    const float LOG_THETA = 9.210340371976184f;
    for (int it = 0; it < 8; it++) {
        int p = threadIdx.x + it * 256;
        int hh = p >> 6, j = p & 63;
        float inv_freq = expf(-(float)j * (LOG_THETA / 64.f));
        float ang = (float)pos * inv_freq;
        float c = cosf(ang), s = sinf(ang);
        size_t base = (size_t)t * DLLM + hh * HD + j;
        float x1 = q[base], x2 = q[base + 64];
        q[base]      = x1 * c - x2 * s;
        q[base + 64] = x2 * c + x1 * s;
        x1 = k[base]; x2 = k[base + 64];
        k[base]      = x1 * c - x2 * s;
        k[base + 64] = x2 * c + x1 * s;
    }
}

__global__ __launch_bounds__(256)
void score_kernel(const float* __restrict__ Q, const float* __restrict__ K,
                  float* __restrict__ Sc)
{
    int bh = blockIdx.z;
    int b = bh >> 5, hh = bh & 31;
    int qi0 = blockIdx.y * 64, kj0 = blockIdx.x * 64;
    __shared__ float As[16][64];
    __shared__ float Bs[16][64];
    int tid = threadIdx.x;
    int tx = tid & 15, ty = tid >> 4;
    float acc[4][4] = {};
    const float* Qb = Q + ((size_t)b * SEQ + qi0) * DLLM + hh * HD;
    const float* Kb = K + ((size_t)b * SEQ + kj0) * DLLM + hh * HD;
    int r  = tid >> 2;
    int c4 = (tid & 3) * 4;
    for (int k0 = 0; k0 < HD; k0 += 16) {
        float4 qa = *(const float4*)(Qb + (size_t)r * DLLM + k0 + c4);
        As[c4+0][r] = qa.x; As[c4+1][r] = qa.y; As[c4+2][r] = qa.z; As[c4+3][r] = qa.w;
        float4 ka = *(const float4*)(Kb + (size_t)r * DLLM + k0 + c4);
        Bs[c4+0][r] = ka.x; Bs[c4+1][r] = ka.y; Bs[c4+2][r] = ka.z; Bs[c4+3][r] = ka.w;
        __syncthreads();
        #pragma unroll
        for (int kk = 0; kk < 16; kk++) {
            float a[4], bb[4];
            *(float4*)a  = *(const float4*)&As[kk][ty * 4];
            *(float4*)bb = *(const float4*)&Bs[kk][tx * 4];
            #pragma unroll
            for (int i = 0; i < 4; i++)
                #pragma unroll
                for (int j = 0; j < 4; j++)
                    acc[i][j] = fmaf(a[i], bb[j], acc[i][j]);
        }
        __syncthreads();
    }
    const float scale = 0.08838834764831845f;
    #pragma unroll
    for (int i = 0; i < 4; i++) {
        int qi = qi0 + ty * 4 + i;
        float* dst = Sc + ((size_t)bh * SEQ + qi) * SEQ + kj0 + tx * 4;
        #pragma unroll
        for (int j = 0; j < 4; j++) {
            int kj = kj0 + tx * 4 + j;
            dst[j] = (kj > qi) ? -1e30f : acc[i][j] * scale;
        }
    }
}

__global__ __launch_bounds__(256)
void softmax_kernel(float* __restrict__ Sc)
{
    float* p = Sc + (size_t)blockIdx.x * SEQ;
    int tid = threadIdx.x;
    __shared__ float redm[8], reds[8];
    float v = p[tid];
    float m = v;
    #pragma unroll
    for (int o = 16; o; o >>= 1) m = fmaxf(m, __shfl_xor_sync(0xffffffffu, m, o));
    if ((tid & 31) == 0) redm[tid >> 5] = m;
    __syncthreads();
    if (tid < 32) {
        float x = (tid < 8) ? redm[tid] : -3.4e38f;
        #pragma unroll
        for (int o = 4; o; o >>= 1) x = fmaxf(x, __shfl_xor_sync(0xffffffffu, x, o));
        if (tid == 0) redm[0] = x;
    }
    __syncthreads();
    m = redm[0];
    float e = expf(v - m);
    float s = e;
    #pragma unroll
    for (int o = 16; o; o >>= 1) s += __shfl_xor_sync(0xffffffffu, s, o);
    if ((tid & 31) == 0) reds[tid >> 5] = s;
    __syncthreads();
    if (tid < 32) {
        float x = (tid < 8) ? reds[tid] : 0.f;
        #pragma unroll
        for (int o = 4; o; o >>= 1) x += __shfl_xor_sync(0xffffffffu, x, o);
        if (tid == 0) reds[0] = x;
    }
    __syncthreads();
    p[tid] = e / reds[0];
}

// attn @ V; epilogue emits split-bf16 A operand for the Wo GEMM
__global__ __launch_bounds__(256)
void av_kernel(const float* __restrict__ P, const float* __restrict__ V,
               unsigned short* __restrict__ Oh, unsigned short* __restrict__ Ol)
{
    int bh = blockIdx.y;
    int b = bh >> 5, hh = bh & 31;
    int qi0 = blockIdx.x * 64;
    __shared__ float Ps[16][64];
    __shared__ float Vs[16][128];
    int tid = threadIdx.x;
    int tx = tid & 31, ty = tid >> 5;
    float acc[8][4] = {};
    const float* Pb = P + ((size_t)bh * SEQ + qi0) * SEQ;
    const float* Vb = V + (size_t)b * SEQ * DLLM + hh * HD;
    int pq = tid >> 2, pk4 = (tid & 3) * 4;
    int vk = tid >> 4, vd8 = (tid & 15) * 8;
    for (int k0 = 0; k0 < SEQ; k0 += 16) {
        float4 pv = *(const float4*)(Pb + (size_t)pq * SEQ + k0 + pk4);
        Ps[pk4+0][pq] = pv.x; Ps[pk4+1][pq] = pv.y; Ps[pk4+2][pq] = pv.z; Ps[pk4+3][pq] = pv.w;
        const float* src = Vb + (size_t)(k0 + vk) * DLLM + vd8;
        *(float4*)&Vs[vk][vd8]     = *(const float4*)(src);
        *(float4*)&Vs[vk][vd8 + 4] = *(const float4*)(src + 4);
        __syncthreads();
        #pragma unroll
        for (int kk = 0; kk < 16; kk++) {
            float a[8], bb[4];
            *(float4*)(a)     = *(const float4*)&Ps[kk][ty * 8];
            *(float4*)(a + 4) = *(const float4*)&Ps[kk][ty * 8 + 4];
            *(float4*)bb      = *(const float4*)&Vs[kk][tx * 4];
            #pragma unroll
            for (int i = 0; i < 8; i++)
                #pragma unroll
                for (int j = 0; j < 4; j++)
                    acc[i][j] = fmaf(a[i], bb[j], acc[i][j]);
        }
        __syncthreads();
    }
    #pragma unroll
    for (int i = 0; i < 8; i++) {
        int qi = qi0 + ty * 8 + i;
        size_t o = ((size_t)b * SEQ + qi) * DLLM + hh * HD + tx * 4;
        ushort4 h, l;
        splitw(acc[i][0], h.x, l.x); splitw(acc[i][1], h.y, l.y);
        splitw(acc[i][2], h.z, l.z); splitw(acc[i][3], h.w, l.w);
        *(ushort4*)(Oh + o) = h;
        *(ushort4*)(Ol + o) = l;
    }
}

__global__ __launch_bounds__(256)
void pool_kernel(const float* __restrict__ x, float* __restrict__ pooled)
{
    int b = blockIdx.x;
    int d = blockIdx.y * 256 + threadIdx.x;
    float s = 0.f;
    const float* base = x + (size_t)b * SEQ * DLLM + d;
    for (int t = 0; t < SEQ; t++) s += base[(size_t)t * DLLM];
    pooled[(size_t)b * DLLM + d] = s * (1.f / SEQ);
}

__global__ __launch_bounds__(256)
void out1_kernel(const float* __restrict__ pooled, const float* __restrict__ W,
                 const float* __restrict__ bias, float* __restrict__ y1)
{
    int b = blockIdx.x;
    int n = blockIdx.y * 256 + threadIdx.x;
    const float* pv = pooled + (size_t)b * DLLM;
    float acc = bias[n];
    for (int k = 0; k < DLLM; k++)
        acc = fmaf(pv[k], W[(size_t)k * 768 + n], acc);
    y1[(size_t)b * 768 + n] = acc;
}

__global__ __launch_bounds__(256)
void out2_kernel(const float* __restrict__ y1, const float* __restrict__ W2,
                 const float* __restrict__ b2, float* __restrict__ out)
{
    int b = blockIdx.x;
    int tid = threadIdx.x;
    __shared__ float red[8];
    float s = 0.f;
    for (int j = tid; j < 768; j += 256) s += y1[(size_t)b * 768 + j] * W2[j];
    #pragma unroll
    for (int o = 16; o; o >>= 1) s += __shfl_xor_sync(0xffffffffu, s, o);
    if ((tid & 31) == 0) red[tid >> 5] = s;
    __syncthreads();
    if (tid < 32) {
        float x = (tid < 8) ? red[tid] : 0.f;
        #pragma unroll
        for (int o = 4; o; o >>= 1) x += __shfl_xor_sync(0xffffffffu, x, o);
        if (tid == 0) out[b] = x + b2[0];
    }
}

// ======================= host orchestration =======================
extern "C" void kernel_launch(void* const* d_in, const int* in_sizes, int n_in,
                              void* d_out, int out_size)
{
    const float* text    = (const float*)d_in[0];
    const float* vision  = (const float*)d_in[1];
    const int*   prompt  = (const int*)  d_in[2];
    const float* in_W    = (const float*)d_in[3];
    const float* in_b    = (const float*)d_in[4];
    const float* table   = (const float*)d_in[5];
    const float* Wq      = (const float*)d_in[6];
    const float* Wk      = (const float*)d_in[7];
    const float* Wv      = (const float*)d_in[8];
    const float* Wo      = (const float*)d_in[9];
    const float* ln1     = (const float*)d_in[10];
    const float* ln2     = (const float*)d_in[11];
    const float* Wg      = (const float*)d_in[12];
    const float* Wu      = (const float*)d_in[13];
    const float* Wd      = (const float*)d_in[14];
    const float* final_w = (const float*)d_in[15];
    const float* out1W   = (const float*)d_in[16];
    const float* out1b   = (const float*)d_in[17];
    const float* out2W   = (const float*)d_in[18];
    const float* out2b   = (const float*)d_in[19];
    float* out = (float*)d_out;

    float *h, *q, *k, *v, *sc, *ff, *ff2, *pooled, *y1;
    unsigned short *ah, *al, *wh, *wl;
    cudaGetSymbolAddress((void**)&h,   g_h);
    cudaGetSymbolAddress((void**)&q,   g_q);
    cudaGetSymbolAddress((void**)&k,   g_k);
    cudaGetSymbolAddress((void**)&v,   g_v);
    cudaGetSymbolAddress((void**)&sc,  g_sc);
    cudaGetSymbolAddress((void**)&ff,  g_ff);
    cudaGetSymbolAddress((void**)&ff2, g_ff2);
    cudaGetSymbolAddress((void**)&pooled, g_pool);
    cudaGetSymbolAddress((void**)&y1,  g_y1);
    cudaGetSymbolAddress((void**)&ah,  a_hi);
    cudaGetSymbolAddress((void**)&al,  a_lo);
    cudaGetSymbolAddress((void**)&wh,  w_hi);
    cudaGetSymbolAddress((void**)&wl,  w_lo);

    cudaFuncSetAttribute(gemm_bf16<0>, cudaFuncAttributeMaxDynamicSharedMemorySize, GSMEM);
    cudaFuncSetAttribute(gemm_bf16<1>, cudaFuncAttributeMaxDynamicSharedMemorySize, GSMEM);

    // ---- inputs into concatenated h: [prompt(128) | text(64) | vision(64)] ----
    embed_kernel<<<B * S_P, 256>>>(prompt, table, h);
    tsplit_kernel<<<dim3(DMODEL/32, DLLM/32, 1), 256>>>(in_W, in_W, in_W, DMODEL, DLLM, wh, wl, 0);
    split_kernel<<<(B*S_T*DMODEL/4 + 255)/256, 256>>>(text, ah, al, B*S_T*DMODEL/4);
    gemm_bf16<0><<<dim3((B*S_T)/128, DLLM/128, 1), 256, GSMEM>>>(
        B*S_T, DLLM, DMODEL, ah, al, wh, wl, 0, in_b, h, h, h, S_T, SEQ, S_P);
    split_kernel<<<(B*S_V*DMODEL/4 + 255)/256, 256>>>(vision, ah, al, B*S_V*DMODEL/4);
    gemm_bf16<0><<<dim3((B*S_V)/128, DLLM/128, 1), 256, GSMEM>>>(
        B*S_V, DLLM, DMODEL, ah, al, wh, wl, 0, in_b, h, h, h, S_V, SEQ, S_P + S_T);

    for (int l = 0; l < NLAYER; l++) {
        const float* wq = Wq + (size_t)l * DLLM * DLLM;
        const float* wk = Wk + (size_t)l * DLLM * DLLM;
        const float* wv = Wv + (size_t)l * DLLM * DLLM;
        const float* wo = Wo + (size_t)l * DLLM * DLLM;
        const float* wg = Wg + (size_t)l * DLLM * DFF;
        const float* wu = Wu + (size_t)l * DLLM * DFF;
        const float* wd = Wd + (size_t)l * DFF * DLLM;
        const float* l1 = ln1 + (size_t)l * DLLM;
        const float* l2 = ln2 + (size_t)l * DLLM;

        // --- attention block ---
        rmsnorm_split_kernel<<<NTOK, 256>>>(h, l1, ah, al);
        tsplit_kernel<<<dim3(DLLM/32, DLLM/32, 3), 256>>>(wq, wk, wv, DLLM, DLLM,
                                                          wh, wl, (size_t)DLLM*DLLM);
        gemm_bf16<0><<<dim3(NTOK/128, DLLM/128, 3), 256, GSMEM>>>(
            NTOK, DLLM, DLLM, ah, al, wh, wl, (size_t)DLLM*DLLM, nullptr,
            q, k, v, NTOK, NTOK, 0);
        rope_kernel<<<NTOK, 256>>>(q, k);
        score_kernel<<<dim3(SEQ/64, SEQ/64, B*NH), 256>>>(q, k, sc);
        softmax_kernel<<<B*NH*SEQ, 256>>>(sc);
        av_kernel<<<dim3(SEQ/64, B*NH), 256>>>(sc, v, ah, al);
        tsplit_kernel<<<dim3(DLLM/32, DLLM/32, 1), 256>>>(wo, wo, wo, DLLM, DLLM, wh, wl, 0);
        gemm_bf16<1><<<dim3(NTOK/128, DLLM/128, 1), 256, GSMEM>>>(
            NTOK, DLLM, DLLM, ah, al, wh, wl, 0, nullptr, h, h, h, NTOK, NTOK, 0);

        // --- FFN block ---
        rmsnorm_split_kernel<<<NTOK, 256>>>(h, l2, ah, al);
        tsplit_kernel<<<dim3(DLLM/32, DFF/32, 2), 256>>>(wg, wu, wu, DLLM, DFF,
                                                         wh, wl, (size_t)DLLM*DFF);
        gemm_bf16<0><<<dim3(NTOK/128, DFF/128, 2), 256, GSMEM>>>(
            NTOK, DFF, DLLM, ah, al, wh, wl, (size_t)DLLM*DFF, nullptr,
            ff, ff2, ff2, NTOK, NTOK, 0);
        swiglu_split_kernel<<<(NTOK*(DFF/4))/256, 256>>>(ff, ff2, ah, al);
        tsplit_kernel<<<dim3(DFF/32, DLLM/32, 1), 256>>>(wd, wd, wd, DFF, DLLM, wh, wl, 0);
        gemm_bf16<1><<<dim3(NTOK/128, DLLM/128, 1), 256, GSMEM>>>(
            NTOK, DLLM, DFF, ah, al, wh, wl, 0, nullptr, h, h, h, NTOK, NTOK, 0);
    }

    rmsnorm_kernel<<<NTOK, 256>>>(h, final_w, q);   // q free: fp32 normed out
    pool_kernel<<<dim3(B, DLLM/256), 256>>>(q, pooled);
    out1_kernel<<<dim3(B, 768/256), 256>>>(pooled, out1W, out1b, y1);
    out2_kernel<<<B, 256>>>(y1, out2W, out2b, out);
}